// round 9
// baseline (speedup 1.0000x reference)
#include <cuda_runtime.h>
#include <cuda_bf16.h>
#include <cstdint>

#define B_  2
#define T_  4096
#define D_  512
#define H_  8
#define HD_ 64
#define M_  (B_*T_)
#define KSTR 72   // smem row stride (bf16): 144B, conflict-free frag loads

// Scratch planes (allocation-free)
__device__ __nv_bfloat16 g_qh[B_*T_*D_], g_ql[B_*T_*D_];
__device__ __nv_bfloat16 g_kh[B_*T_*D_], g_kl[B_*T_*D_];
__device__ __nv_bfloat16 g_vth[B_*T_*D_], g_vtl[B_*T_*D_];  // V transposed [bh][hd][T]
__device__ __nv_bfloat16 g_ch[B_*T_*D_], g_cl[B_*T_*D_];    // ctx planes
__device__ __nv_bfloat16 g_xh[M_*D_],    g_xl[M_*D_];       // token_embed planes
__device__ __nv_bfloat16 g_wh[4][D_*D_], g_wl[4][D_*D_];    // Wq,Wk,Wv,Wo planes

// ---------------------------------------------------------------------------
__device__ __forceinline__ void mma16816(float* c, const uint32_t* a, const uint32_t* b) {
    asm volatile(
        "mma.sync.aligned.m16n8k16.row.col.f32.bf16.bf16.f32 "
        "{%0,%1,%2,%3}, {%4,%5,%6,%7}, {%8,%9}, {%0,%1,%2,%3};"
        : "+f"(c[0]), "+f"(c[1]), "+f"(c[2]), "+f"(c[3])
        : "r"(a[0]), "r"(a[1]), "r"(a[2]), "r"(a[3]), "r"(b[0]), "r"(b[1]));
}

__device__ __forceinline__ void cpa16(uint32_t dst, const void* src) {
    asm volatile("cp.async.cg.shared.global [%0], [%1], 16;" :: "r"(dst), "l"(src));
}
#define CP_COMMIT() asm volatile("cp.async.commit_group;" ::: "memory")
#define CP_WAIT0()  asm volatile("cp.async.wait_group 0;" ::: "memory")

__device__ __forceinline__ float fexp2(float x) {
    float t = x + 12582912.0f;
    int   n = __float_as_int(t) - __float_as_int(12582912.0f);
    float f = x - (t - 12582912.0f);
    float p = 1.3333558146e-3f;
    p = fmaf(p, f, 9.6181291076e-3f);
    p = fmaf(p, f, 5.5504108664e-2f);
    p = fmaf(p, f, 2.4022650696e-1f);
    p = fmaf(p, f, 6.9314718056e-1f);
    p = fmaf(p, f, 1.0f);
    return p * __int_as_float((n + 127) << 23);
}

__device__ __forceinline__ uint32_t packbf(float a, float b) {
    __nv_bfloat162 h = __floats2bfloat162_rn(a, b);
    return *(uint32_t*)&h;
}

// ---------------------------------------------------------------------------
__global__ __launch_bounds__(256) void split_f32(
    const float* __restrict__ in, __nv_bfloat16* __restrict__ hi,
    __nv_bfloat16* __restrict__ lo, int n4)
{
    const int i = blockIdx.x * blockDim.x + threadIdx.x;
    if (i >= n4) return;
    float4 x = ((const float4*)in)[i];
    __nv_bfloat162 h0 = __floats2bfloat162_rn(x.x, x.y);
    __nv_bfloat162 h1 = __floats2bfloat162_rn(x.z, x.w);
    float2 f0 = __bfloat1622float2(h0);
    float2 f1 = __bfloat1622float2(h1);
    ((__nv_bfloat162*)hi)[2*i]     = h0;
    ((__nv_bfloat162*)hi)[2*i + 1] = h1;
    ((__nv_bfloat162*)lo)[2*i]     = __floats2bfloat162_rn(x.x - f0.x, x.y - f0.y);
    ((__nv_bfloat162*)lo)[2*i + 1] = __floats2bfloat162_rn(x.z - f1.x, x.w - f1.y);
}

// ===========================================================================
// Split-bf16 HMMA GEMM: C = A @ W^T (3-term compensation).
// MODE 0: fp32 out + bias. MODE 1: bf16 hi/lo head layout [bh][t][hd].
// MODE 2: bf16 hi/lo transposed head layout [bh][hd][t]  (for V).
// ===========================================================================
template <int MODE>
__global__ __launch_bounds__(256) void gemm_hmma(
    const __nv_bfloat16* __restrict__ Ah, const __nv_bfloat16* __restrict__ Al,
    const __nv_bfloat16* __restrict__ Wh, const __nv_bfloat16* __restrict__ Wl,
    const float* __restrict__ bias, float* __restrict__ Cf,
    __nv_bfloat16* __restrict__ Ch, __nv_bfloat16* __restrict__ Cl)
{
    extern __shared__ __nv_bfloat16 sm[];
    __nv_bfloat16 (*sAh)[KSTR] = (__nv_bfloat16(*)[KSTR])(sm);
    __nv_bfloat16 (*sAl)[KSTR] = (__nv_bfloat16(*)[KSTR])(sm + 128 * KSTR);
    __nv_bfloat16 (*sWh)[KSTR] = (__nv_bfloat16(*)[KSTR])(sm + 256 * KSTR);
    __nv_bfloat16 (*sWl)[KSTR] = (__nv_bfloat16(*)[KSTR])(sm + 320 * KSTR);

    const int tid = threadIdx.x, wid = tid >> 5, lane = tid & 31;
    const int g = lane >> 2, tig = lane & 3;
    const int m0 = blockIdx.y * 128, n0 = blockIdx.x * 64;

    const int ar = tid >> 1, ad0 = (tid & 1) * 32;
    const int wr = tid >> 2, wd0 = (tid & 3) * 16;

    float acc[8][4];
#pragma unroll
    for (int i = 0; i < 8; i++)
#pragma unroll
        for (int j = 0; j < 4; j++) acc[i][j] = 0.f;

    for (int k0 = 0; k0 < D_; k0 += 64) {
        __syncthreads();
        {
            const __nv_bfloat16* pa = Ah + (size_t)(m0 + ar) * D_ + k0 + ad0;
            const __nv_bfloat16* pl = Al + (size_t)(m0 + ar) * D_ + k0 + ad0;
#pragma unroll
            for (int u = 0; u < 4; u++) {
                *(uint4*)&sAh[ar][ad0 + u * 8] = *(const uint4*)(pa + u * 8);
                *(uint4*)&sAl[ar][ad0 + u * 8] = *(const uint4*)(pl + u * 8);
            }
            const __nv_bfloat16* pw = Wh + (size_t)(n0 + wr) * D_ + k0 + wd0;
            const __nv_bfloat16* pq = Wl + (size_t)(n0 + wr) * D_ + k0 + wd0;
#pragma unroll
            for (int u = 0; u < 2; u++) {
                *(uint4*)&sWh[wr][wd0 + u * 8] = *(const uint4*)(pw + u * 8);
                *(uint4*)&sWl[wr][wd0 + u * 8] = *(const uint4*)(pq + u * 8);
            }
        }
        __syncthreads();

        uint32_t ah[4][4], al[4][4];
        const int r0 = wid * 16 + g;
#pragma unroll
        for (int kt = 0; kt < 4; kt++) {
            const int c0 = kt * 16 + tig * 2;
            ah[kt][0] = *(uint32_t*)&sAh[r0    ][c0    ];
            ah[kt][1] = *(uint32_t*)&sAh[r0 + 8][c0    ];
            ah[kt][2] = *(uint32_t*)&sAh[r0    ][c0 + 8];
            ah[kt][3] = *(uint32_t*)&sAh[r0 + 8][c0 + 8];
            al[kt][0] = *(uint32_t*)&sAl[r0    ][c0    ];
            al[kt][1] = *(uint32_t*)&sAl[r0 + 8][c0    ];
            al[kt][2] = *(uint32_t*)&sAl[r0    ][c0 + 8];
            al[kt][3] = *(uint32_t*)&sAl[r0 + 8][c0 + 8];
        }
#pragma unroll
        for (int nt = 0; nt < 8; nt++) {
            const int row = nt * 8 + g;
            uint32_t bh[4][2], bl[4][2];
#pragma unroll
            for (int kk = 0; kk < 4; kk++) {
                const int c = kk * 16 + tig * 2;
                bh[kk][0] = *(uint32_t*)&sWh[row][c];
                bh[kk][1] = *(uint32_t*)&sWh[row][c + 8];
                bl[kk][0] = *(uint32_t*)&sWl[row][c];
                bl[kk][1] = *(uint32_t*)&sWl[row][c + 8];
            }
#pragma unroll
            for (int kk = 0; kk < 4; kk++) mma16816(acc[nt], ah[kk], bh[kk]);
#pragma unroll
            for (int kk = 0; kk < 4; kk++) mma16816(acc[nt], al[kk], bh[kk]);
#pragma unroll
            for (int kk = 0; kk < 4; kk++) mma16816(acc[nt], ah[kk], bl[kk]);
        }
    }

    const int gm = m0 + wid * 16 + g;
#pragma unroll
    for (int nt = 0; nt < 8; nt++) {
        const int n = n0 + nt * 8 + tig * 2;
        if (MODE == 0) {
            const float bx = bias[n], by = bias[n + 1];
            *(float2*)(Cf + (size_t)gm * D_ + n) =
                make_float2(acc[nt][0] + bx, acc[nt][1] + by);
            *(float2*)(Cf + (size_t)(gm + 8) * D_ + n) =
                make_float2(acc[nt][2] + bx, acc[nt][3] + by);
        } else if (MODE == 1) {
            const int b = gm >> 12, t = gm & (T_ - 1);
            const int h = n >> 6, hd = n & 63;
            const size_t i0 = (((size_t)(b * H_ + h)) * T_ + t) * HD_ + hd;
            const size_t i1 = i0 + 8 * HD_;
            __nv_bfloat162 h0 = __floats2bfloat162_rn(acc[nt][0], acc[nt][1]);
            __nv_bfloat162 h1 = __floats2bfloat162_rn(acc[nt][2], acc[nt][3]);
            float2 f0 = __bfloat1622float2(h0);
            float2 f1 = __bfloat1622float2(h1);
            *(__nv_bfloat162*)(Ch + i0) = h0;
            *(__nv_bfloat162*)(Ch + i1) = h1;
            *(__nv_bfloat162*)(Cl + i0) = __floats2bfloat162_rn(acc[nt][0] - f0.x, acc[nt][1] - f0.y);
            *(__nv_bfloat162*)(Cl + i1) = __floats2bfloat162_rn(acc[nt][2] - f1.x, acc[nt][3] - f1.y);
        } else {   // MODE 2: transposed V planes [bh][hd][t]
            const int b = gm >> 12, t = gm & (T_ - 1);
            const int h = n >> 6, hd = n & 63;
            const size_t r0i = (((size_t)(b * H_ + h)) * HD_ + hd) * T_;
#pragma unroll
            for (int e = 0; e < 2; e++) {
                float v0 = acc[nt][e];         // (t,     n+e)
                float v1 = acc[nt][2 + e];     // (t + 8, n+e)
                __nv_bfloat16 h0 = __float2bfloat16(v0);
                __nv_bfloat16 h1 = __float2bfloat16(v1);
                const size_t ix = r0i + (size_t)e * T_ + t;
                Ch[ix]     = h0;
                Ch[ix + 8] = h1;
                Cl[ix]     = __float2bfloat16(v0 - __bfloat162float(h0));
                Cl[ix + 8] = __float2bfloat16(v1 - __bfloat162float(h1));
            }
        }
    }
}
#define GEMM_SMEM ((384 * KSTR) * 2)   // 55296 bytes

// ===========================================================================
// Causal flash attention: cp.async double-buffered K/V tiles, V pre-transposed
// globally. BQ=128, BK=64, 256 threads (8 warps).
// ===========================================================================
#define BQ 128
#define BK 64
#define SBUF (4 * BK * KSTR)           // bf16 elems per buffer (Kh,Kl,Vh,Vl)
#define FLASH_SMEM (2 * SBUF * 2)      // 73728 bytes

__global__ __launch_bounds__(256) void flash_mma(
    const __nv_bfloat16* __restrict__ Qh, const __nv_bfloat16* __restrict__ Ql,
    const __nv_bfloat16* __restrict__ Kh, const __nv_bfloat16* __restrict__ Kl,
    const __nv_bfloat16* __restrict__ Vth, const __nv_bfloat16* __restrict__ Vtl,
    __nv_bfloat16* __restrict__ Ch, __nv_bfloat16* __restrict__ Cl)
{
    extern __shared__ __nv_bfloat16 sm[];
    const uint32_t sbase = (uint32_t)__cvta_generic_to_shared(sm);

    const int tid  = threadIdx.x;
    const int wid  = tid >> 5, lane = tid & 31;
    const int g    = lane >> 2, tig = lane & 3;
    const int bh   = blockIdx.y;
    const int q0   = (gridDim.x - 1 - blockIdx.x) * BQ;

    const size_t base = (size_t)bh * T_ * HD_;
    const __nv_bfloat16* Qhg = Qh + base;  const __nv_bfloat16* Qlg = Ql + base;
    const __nv_bfloat16* Khg = Kh + base;  const __nv_bfloat16* Klg = Kl + base;
    const __nv_bfloat16* Vhg = Vth + base; const __nv_bfloat16* Vlg = Vtl + base;

    // ---- Stage Q through buffer-0 K planes, extract A-frags ----
    __nv_bfloat16 (*qsH)[KSTR] = (__nv_bfloat16(*)[KSTR])(sm);
    __nv_bfloat16 (*qsL)[KSTR] = (__nv_bfloat16(*)[KSTR])(sm + BK * KSTR);
    uint32_t qhf[4][4], qlf[4][4];
    const int cprow = tid >> 2;
    const int cpd0  = (tid & 3) * 16;
#pragma unroll
    for (int pb = 0; pb < 2; pb++) {
        if (pb) __syncthreads();
        {
            const __nv_bfloat16* s0 = Qhg + (size_t)(q0 + pb * 64 + cprow) * HD_ + cpd0;
            const __nv_bfloat16* s1 = Qlg + (size_t)(q0 + pb * 64 + cprow) * HD_ + cpd0;
            *(uint4*)&qsH[cprow][cpd0]     = *(const uint4*)(s0);
            *(uint4*)&qsH[cprow][cpd0 + 8] = *(const uint4*)(s0 + 8);
            *(uint4*)&qsL[cprow][cpd0]     = *(const uint4*)(s1);
            *(uint4*)&qsL[cprow][cpd0 + 8] = *(const uint4*)(s1 + 8);
        }
        __syncthreads();
        if ((wid >> 2) == pb) {
            const int r0 = (wid & 3) * 16 + g;
#pragma unroll
            for (int kt = 0; kt < 4; kt++) {
                const int c0 = kt * 16 + tig * 2;
                qhf[kt][0] = *(uint32_t*)&qsH[r0    ][c0    ];
                qhf[kt][1] = *(uint32_t*)&qsH[r0 + 8][c0    ];
                qhf[kt][2] = *(uint32_t*)&qsH[r0    ][c0 + 8];
                qhf[kt][3] = *(uint32_t*)&qsH[r0 + 8][c0 + 8];
                qlf[kt][0] = *(uint32_t*)&qsL[r0    ][c0    ];
                qlf[kt][1] = *(uint32_t*)&qsL[r0 + 8][c0    ];
                qlf[kt][2] = *(uint32_t*)&qsL[r0    ][c0 + 8];
                qlf[kt][3] = *(uint32_t*)&qsL[r0 + 8][c0 + 8];
            }
        }
    }
    __syncthreads();   // Q frag reads done before cp.async overwrites buffer 0

    // ---- Prefetch helper: 8 x 16B cp.async per thread per tile ----
    const int pr = tid >> 2;            // 0..63 (K row / V hd row)
    const int pe = (tid & 3) * 16;      // elem offset 0,16,32,48
    const __nv_bfloat16* kh_src = Khg + (size_t)pr * HD_ + pe;
    const __nv_bfloat16* kl_src = Klg + (size_t)pr * HD_ + pe;
    const __nv_bfloat16* vh_src = Vhg + (size_t)pr * T_ + pe;
    const __nv_bfloat16* vl_src = Vlg + (size_t)pr * T_ + pe;
    const uint32_t drow = sbase + (uint32_t)(pr * KSTR + pe) * 2;

    auto prefetch = [&](int jt, int b) {
        const int k0 = jt * BK;
        const uint32_t d0 = drow + (uint32_t)b * (SBUF * 2);
        const __nv_bfloat16* s;
        s = kh_src + (size_t)k0 * HD_;
        cpa16(d0, s); cpa16(d0 + 16, s + 8);
        s = kl_src + (size_t)k0 * HD_;
        cpa16(d0 + BK * KSTR * 2, s); cpa16(d0 + BK * KSTR * 2 + 16, s + 8);
        s = vh_src + k0;
        cpa16(d0 + 2 * BK * KSTR * 2, s); cpa16(d0 + 2 * BK * KSTR * 2 + 16, s + 8);
        s = vl_src + k0;
        cpa16(d0 + 3 * BK * KSTR * 2, s); cpa16(d0 + 3 * BK * KSTR * 2 + 16, s + 8);
    };

    float O[8][4];
#pragma unroll
    for (int i = 0; i < 8; i++)
#pragma unroll
        for (int j = 0; j < 4; j++) O[i][j] = 0.f;
    float l0 = 0.f, l1 = 0.f;

    const float SC = 0.18033688011112042f;
    const int r0g = q0 + wid * 16 + g;
    const int r1g = r0g + 8;
    const int ntiles = (q0 >> 6) + 2;

    prefetch(0, 0);
    CP_COMMIT();

    for (int jt = 0; jt < ntiles; jt++) {
        const int k0 = jt * BK;
        CP_WAIT0();
        __syncthreads();
        if (jt + 1 < ntiles) { prefetch(jt + 1, (jt + 1) & 1); CP_COMMIT(); }

        __nv_bfloat16 (*cKh)[KSTR] = (__nv_bfloat16(*)[KSTR])(sm + (jt & 1) * SBUF);
        __nv_bfloat16 (*cKl)[KSTR] = (__nv_bfloat16(*)[KSTR])(sm + (jt & 1) * SBUF + BK * KSTR);
        __nv_bfloat16 (*cVh)[KSTR] = (__nv_bfloat16(*)[KSTR])(sm + (jt & 1) * SBUF + 2 * BK * KSTR);
        __nv_bfloat16 (*cVl)[KSTR] = (__nv_bfloat16(*)[KSTR])(sm + (jt & 1) * SBUF + 3 * BK * KSTR);

        if (jt == ntiles - 1 && wid < 4) continue;
        const bool needmask = (jt >= ntiles - 2);

#pragma unroll
        for (int kt = 0; kt < 4; kt++) {
            uint32_t pa_h[4], pa_l[4];
#pragma unroll
            for (int half = 0; half < 2; half++) {
                const int nt = 2 * kt + half;
                float c[4] = {0.f, 0.f, 0.f, 0.f};
                uint32_t bf[4][2];
#pragma unroll
                for (int kk = 0; kk < 4; kk++) {
                    const int row = nt * 8 + g, col = kk * 16 + tig * 2;
                    bf[kk][0] = *(uint32_t*)&cKh[row][col];
                    bf[kk][1] = *(uint32_t*)&cKh[row][col + 8];
                }
#pragma unroll
                for (int kk = 0; kk < 4; kk++) mma16816(c, qhf[kk], bf[kk]);
#pragma unroll
                for (int kk = 0; kk < 4; kk++) mma16816(c, qlf[kk], bf[kk]);
#pragma unroll
                for (int kk = 0; kk < 4; kk++) {
                    const int row = nt * 8 + g, col = kk * 16 + tig * 2;
                    bf[kk][0] = *(uint32_t*)&cKl[row][col];
                    bf[kk][1] = *(uint32_t*)&cKl[row][col + 8];
                }
#pragma unroll
                for (int kk = 0; kk < 4; kk++) mma16816(c, qhf[kk], bf[kk]);

                const int kp = k0 + nt * 8 + tig * 2;
                float p00 = fexp2(c[0] * SC), p01 = fexp2(c[1] * SC);
                float p10 = fexp2(c[2] * SC), p11 = fexp2(c[3] * SC);
                if (needmask) {
                    if (kp     > r0g) p00 = 0.f;
                    if (kp + 1 > r0g) p01 = 0.f;
                    if (kp     > r1g) p10 = 0.f;
                    if (kp + 1 > r1g) p11 = 0.f;
                }
                l0 += p00 + p01;
                l1 += p10 + p11;
                uint32_t h0 = packbf(p00, p01), h1 = packbf(p10, p11);
                float2 f0 = __bfloat1622float2(*(__nv_bfloat162*)&h0);
                float2 f1 = __bfloat1622float2(*(__nv_bfloat162*)&h1);
                pa_h[half*2 + 0] = h0;
                pa_h[half*2 + 1] = h1;
                pa_l[half*2 + 0] = packbf(p00 - f0.x, p01 - f0.y);
                pa_l[half*2 + 1] = packbf(p10 - f1.x, p11 - f1.y);
            }
#pragma unroll
            for (int dn = 0; dn < 8; dn++) {
                const int d = dn * 8 + g;
                const int c0 = kt * 16 + tig * 2;
                uint32_t bv[2], bvl[2];
                bv[0]  = *(uint32_t*)&cVh[d][c0];
                bv[1]  = *(uint32_t*)&cVh[d][c0 + 8];
                bvl[0] = *(uint32_t*)&cVl[d][c0];
                bvl[1] = *(uint32_t*)&cVl[d][c0 + 8];
                mma16816(O[dn], pa_h, bv);
                mma16816(O[dn], pa_l, bv);
                mma16816(O[dn], pa_h, bvl);
            }
        }
    }

    l0 += __shfl_xor_sync(0xffffffffu, l0, 1);
    l0 += __shfl_xor_sync(0xffffffffu, l0, 2);
    l1 += __shfl_xor_sync(0xffffffffu, l1, 1);
    l1 += __shfl_xor_sync(0xffffffffu, l1, 2);
    const float i0 = 1.0f / l0, i1 = 1.0f / l1;

    const int b = bh >> 3, h = bh & 7;
    const size_t o0 = ((size_t)(b * T_ + r0g)) * D_ + h * HD_;
    const size_t o1 = ((size_t)(b * T_ + r1g)) * D_ + h * HD_;
#pragma unroll
    for (int dn = 0; dn < 8; dn++) {
        const int d = dn * 8 + tig * 2;
        float a0 = O[dn][0] * i0, a1 = O[dn][1] * i0;
        float b0 = O[dn][2] * i1, b1 = O[dn][3] * i1;
        __nv_bfloat162 h0 = __floats2bfloat162_rn(a0, a1);
        __nv_bfloat162 h1 = __floats2bfloat162_rn(b0, b1);
        float2 f0 = __bfloat1622float2(h0);
        float2 f1 = __bfloat1622float2(h1);
        *(__nv_bfloat162*)(Ch + o0 + d) = h0;
        *(__nv_bfloat162*)(Ch + o1 + d) = h1;
        *(__nv_bfloat162*)(Cl + o0 + d) = __floats2bfloat162_rn(a0 - f0.x, a1 - f0.y);
        *(__nv_bfloat162*)(Cl + o1 + d) = __floats2bfloat162_rn(b0 - f1.x, b1 - f1.y);
    }
}

// ===========================================================================
extern "C" void kernel_launch(void* const* d_in, const int* in_sizes, int n_in,
                              void* d_out, int out_size)
{
    const float* x  = (const float*)d_in[0];
    const float* Wq = (const float*)d_in[1];
    const float* Wk = (const float*)d_in[2];
    const float* Wv = (const float*)d_in[3];
    const float* Wo = (const float*)d_in[4];
    const float* bo = (const float*)d_in[5];
    float* out = (float*)d_out;

    __nv_bfloat16 *qh, *ql, *kh, *kl, *vth, *vtl, *ch, *cl, *xh, *xl, *wh, *wl;
    cudaGetSymbolAddress((void**)&qh, g_qh); cudaGetSymbolAddress((void**)&ql, g_ql);
    cudaGetSymbolAddress((void**)&kh, g_kh); cudaGetSymbolAddress((void**)&kl, g_kl);
    cudaGetSymbolAddress((void**)&vth, g_vth); cudaGetSymbolAddress((void**)&vtl, g_vtl);
    cudaGetSymbolAddress((void**)&ch, g_ch); cudaGetSymbolAddress((void**)&cl, g_cl);
    cudaGetSymbolAddress((void**)&xh, g_xh); cudaGetSymbolAddress((void**)&xl, g_xl);
    cudaGetSymbolAddress((void**)&wh, g_wh); cudaGetSymbolAddress((void**)&wl, g_wl);

    static bool attr_done = false;
    if (!attr_done) {
        cudaFuncSetAttribute(gemm_hmma<0>, cudaFuncAttributeMaxDynamicSharedMemorySize, GEMM_SMEM);
        cudaFuncSetAttribute(gemm_hmma<1>, cudaFuncAttributeMaxDynamicSharedMemorySize, GEMM_SMEM);
        cudaFuncSetAttribute(gemm_hmma<2>, cudaFuncAttributeMaxDynamicSharedMemorySize, GEMM_SMEM);
        cudaFuncSetAttribute(flash_mma, cudaFuncAttributeMaxDynamicSharedMemorySize, FLASH_SMEM);
        attr_done = true;
    }

    split_f32<<<(M_ * D_ / 4 + 255) / 256, 256>>>(x,  xh, xl, M_ * D_ / 4);
    split_f32<<<(D_ * D_ / 4 + 255) / 256, 256>>>(Wq, wh + 0 * (size_t)D_ * D_, wl + 0 * (size_t)D_ * D_, D_ * D_ / 4);
    split_f32<<<(D_ * D_ / 4 + 255) / 256, 256>>>(Wk, wh + 1 * (size_t)D_ * D_, wl + 1 * (size_t)D_ * D_, D_ * D_ / 4);
    split_f32<<<(D_ * D_ / 4 + 255) / 256, 256>>>(Wv, wh + 2 * (size_t)D_ * D_, wl + 2 * (size_t)D_ * D_, D_ * D_ / 4);
    split_f32<<<(D_ * D_ / 4 + 255) / 256, 256>>>(Wo, wh + 3 * (size_t)D_ * D_, wl + 3 * (size_t)D_ * D_, D_ * D_ / 4);

    dim3 ggrid(D_ / 64, M_ / 128);   // (8, 64)

    gemm_hmma<1><<<ggrid, 256, GEMM_SMEM>>>(xh, xl, wh + 0 * (size_t)D_ * D_, wl + 0 * (size_t)D_ * D_,
                                            nullptr, nullptr, qh, ql);
    gemm_hmma<1><<<ggrid, 256, GEMM_SMEM>>>(xh, xl, wh + 1 * (size_t)D_ * D_, wl + 1 * (size_t)D_ * D_,
                                            nullptr, nullptr, kh, kl);
    gemm_hmma<2><<<ggrid, 256, GEMM_SMEM>>>(xh, xl, wh + 2 * (size_t)D_ * D_, wl + 2 * (size_t)D_ * D_,
                                            nullptr, nullptr, vth, vtl);

    dim3 agrid(T_ / BQ, B_ * H_);    // (32, 16)
    flash_mma<<<agrid, 256, FLASH_SMEM>>>(qh, ql, kh, kl, vth, vtl, ch, cl);

    gemm_hmma<0><<<ggrid, 256, GEMM_SMEM>>>(ch, cl, wh + 3 * (size_t)D_ * D_, wl + 3 * (size_t)D_ * D_,
                                            bo, out, nullptr, nullptr);
}

// round 10
// speedup vs baseline: 1.0279x; 1.0279x over previous
#include <cuda_runtime.h>
#include <cuda_bf16.h>
#include <cstdint>

#define B_  2
#define T_  4096
#define D_  512
#define H_  8
#define HD_ 64
#define M_  (B_*T_)
#define KSTR 72   // smem row stride (bf16): 144B, conflict-free frag loads

// Scratch planes (allocation-free)
__device__ __nv_bfloat16 g_qh[B_*T_*D_], g_ql[B_*T_*D_];
__device__ __nv_bfloat16 g_kh[B_*T_*D_], g_kl[B_*T_*D_];
__device__ __nv_bfloat16 g_vth[B_*T_*D_], g_vtl[B_*T_*D_];  // V transposed [bh][hd][T]
__device__ __nv_bfloat16 g_ch[B_*T_*D_], g_cl[B_*T_*D_];    // ctx planes
__device__ __nv_bfloat16 g_xh[M_*D_],    g_xl[M_*D_];       // token_embed planes
__device__ __nv_bfloat16 g_wh[4][D_*D_], g_wl[4][D_*D_];    // Wq,Wk,Wv,Wo planes

// ---------------------------------------------------------------------------
__device__ __forceinline__ void mma16816(float* c, const uint32_t* a, const uint32_t* b) {
    asm volatile(
        "mma.sync.aligned.m16n8k16.row.col.f32.bf16.bf16.f32 "
        "{%0,%1,%2,%3}, {%4,%5,%6,%7}, {%8,%9}, {%0,%1,%2,%3};"
        : "+f"(c[0]), "+f"(c[1]), "+f"(c[2]), "+f"(c[3])
        : "r"(a[0]), "r"(a[1]), "r"(a[2]), "r"(a[3]), "r"(b[0]), "r"(b[1]));
}

__device__ __forceinline__ void cpa16(uint32_t dst, const void* src) {
    asm volatile("cp.async.cg.shared.global [%0], [%1], 16;" :: "r"(dst), "l"(src));
}
#define CP_COMMIT() asm volatile("cp.async.commit_group;" ::: "memory")
#define CP_WAIT0()  asm volatile("cp.async.wait_group 0;" ::: "memory")

__device__ __forceinline__ float fexp2(float x) {
    float t = x + 12582912.0f;
    int   n = __float_as_int(t) - __float_as_int(12582912.0f);
    float f = x - (t - 12582912.0f);
    float p = 1.3333558146e-3f;
    p = fmaf(p, f, 9.6181291076e-3f);
    p = fmaf(p, f, 5.5504108664e-2f);
    p = fmaf(p, f, 2.4022650696e-1f);
    p = fmaf(p, f, 6.9314718056e-1f);
    p = fmaf(p, f, 1.0f);
    return p * __int_as_float((n + 127) << 23);
}

__device__ __forceinline__ uint32_t packbf(float a, float b) {
    __nv_bfloat162 h = __floats2bfloat162_rn(a, b);
    return *(uint32_t*)&h;
}

// ---------------------------------------------------------------------------
__global__ __launch_bounds__(256) void split_f32(
    const float* __restrict__ in, __nv_bfloat16* __restrict__ hi,
    __nv_bfloat16* __restrict__ lo, int n4)
{
    const int i = blockIdx.x * blockDim.x + threadIdx.x;
    if (i >= n4) return;
    float4 x = ((const float4*)in)[i];
    __nv_bfloat162 h0 = __floats2bfloat162_rn(x.x, x.y);
    __nv_bfloat162 h1 = __floats2bfloat162_rn(x.z, x.w);
    float2 f0 = __bfloat1622float2(h0);
    float2 f1 = __bfloat1622float2(h1);
    ((__nv_bfloat162*)hi)[2*i]     = h0;
    ((__nv_bfloat162*)hi)[2*i + 1] = h1;
    ((__nv_bfloat162*)lo)[2*i]     = __floats2bfloat162_rn(x.x - f0.x, x.y - f0.y);
    ((__nv_bfloat162*)lo)[2*i + 1] = __floats2bfloat162_rn(x.z - f1.x, x.w - f1.y);
}

// ===========================================================================
// Split-bf16 HMMA GEMM, cp.async double-buffered K loop.
// MODE 0: fp32 out + bias. MODE 1: bf16 hi/lo head layout [bh][t][hd].
// MODE 2: bf16 hi/lo transposed head layout [bh][hd][t]  (for V).
// ===========================================================================
#define GBUF (384 * KSTR)              // bf16 elems per buffer
#define GEMM_SMEM (2 * GBUF * 2)       // 110592 bytes

template <int MODE>
__global__ __launch_bounds__(256, 2) void gemm_hmma(
    const __nv_bfloat16* __restrict__ Ah, const __nv_bfloat16* __restrict__ Al,
    const __nv_bfloat16* __restrict__ Wh, const __nv_bfloat16* __restrict__ Wl,
    const float* __restrict__ bias, float* __restrict__ Cf,
    __nv_bfloat16* __restrict__ Ch, __nv_bfloat16* __restrict__ Cl)
{
    extern __shared__ __nv_bfloat16 sm[];
    const uint32_t sbase = (uint32_t)__cvta_generic_to_shared(sm);

    const int tid = threadIdx.x, wid = tid >> 5, lane = tid & 31;
    const int g = lane >> 2, tig = lane & 3;
    const int m0 = blockIdx.y * 128, n0 = blockIdx.x * 64;

    const int ar = tid >> 1, ad0 = (tid & 1) * 32;
    const int wr = tid >> 2, wd0 = (tid & 3) * 16;

    const __nv_bfloat16* pa_src = Ah + (size_t)(m0 + ar) * D_ + ad0;
    const __nv_bfloat16* pl_src = Al + (size_t)(m0 + ar) * D_ + ad0;
    const __nv_bfloat16* pw_src = Wh + (size_t)(n0 + wr) * D_ + wd0;
    const __nv_bfloat16* pq_src = Wl + (size_t)(n0 + wr) * D_ + wd0;
    const uint32_t da = sbase + (uint32_t)(ar * KSTR + ad0) * 2;
    const uint32_t dw = sbase + (uint32_t)(256 * KSTR + wr * KSTR + wd0) * 2;

    auto prefetch = [&](int k0, int b) {
        const uint32_t off = (uint32_t)b * (GBUF * 2);
        const __nv_bfloat16* s;
        s = pa_src + k0;
#pragma unroll
        for (int u = 0; u < 4; u++) cpa16(da + off + u * 16, s + u * 8);
        s = pl_src + k0;
#pragma unroll
        for (int u = 0; u < 4; u++) cpa16(da + off + 128 * KSTR * 2 + u * 16, s + u * 8);
        s = pw_src + k0;
#pragma unroll
        for (int u = 0; u < 2; u++) cpa16(dw + off + u * 16, s + u * 8);
        s = pq_src + k0;
#pragma unroll
        for (int u = 0; u < 2; u++) cpa16(dw + off + 64 * KSTR * 2 + u * 16, s + u * 8);
    };

    float acc[8][4];
#pragma unroll
    for (int i = 0; i < 8; i++)
#pragma unroll
        for (int j = 0; j < 4; j++) acc[i][j] = 0.f;

    prefetch(0, 0);
    CP_COMMIT();

    for (int it = 0; it < 8; it++) {
        CP_WAIT0();
        __syncthreads();
        if (it + 1 < 8) { prefetch((it + 1) * 64, (it + 1) & 1); CP_COMMIT(); }

        const __nv_bfloat16* buf = sm + (it & 1) * GBUF;
        __nv_bfloat16 (*sAh)[KSTR] = (__nv_bfloat16(*)[KSTR])(buf);
        __nv_bfloat16 (*sAl)[KSTR] = (__nv_bfloat16(*)[KSTR])(buf + 128 * KSTR);
        __nv_bfloat16 (*sWh)[KSTR] = (__nv_bfloat16(*)[KSTR])(buf + 256 * KSTR);
        __nv_bfloat16 (*sWl)[KSTR] = (__nv_bfloat16(*)[KSTR])(buf + 320 * KSTR);

        uint32_t ah[4][4], al[4][4];
        const int r0 = wid * 16 + g;
#pragma unroll
        for (int kt = 0; kt < 4; kt++) {
            const int c0 = kt * 16 + tig * 2;
            ah[kt][0] = *(uint32_t*)&sAh[r0    ][c0    ];
            ah[kt][1] = *(uint32_t*)&sAh[r0 + 8][c0    ];
            ah[kt][2] = *(uint32_t*)&sAh[r0    ][c0 + 8];
            ah[kt][3] = *(uint32_t*)&sAh[r0 + 8][c0 + 8];
            al[kt][0] = *(uint32_t*)&sAl[r0    ][c0    ];
            al[kt][1] = *(uint32_t*)&sAl[r0 + 8][c0    ];
            al[kt][2] = *(uint32_t*)&sAl[r0    ][c0 + 8];
            al[kt][3] = *(uint32_t*)&sAl[r0 + 8][c0 + 8];
        }
#pragma unroll
        for (int nt = 0; nt < 8; nt++) {
            const int row = nt * 8 + g;
            uint32_t bh[4][2], bl[4][2];
#pragma unroll
            for (int kk = 0; kk < 4; kk++) {
                const int c = kk * 16 + tig * 2;
                bh[kk][0] = *(uint32_t*)&sWh[row][c];
                bh[kk][1] = *(uint32_t*)&sWh[row][c + 8];
                bl[kk][0] = *(uint32_t*)&sWl[row][c];
                bl[kk][1] = *(uint32_t*)&sWl[row][c + 8];
            }
#pragma unroll
            for (int kk = 0; kk < 4; kk++) mma16816(acc[nt], ah[kk], bh[kk]);
#pragma unroll
            for (int kk = 0; kk < 4; kk++) mma16816(acc[nt], al[kk], bh[kk]);
#pragma unroll
            for (int kk = 0; kk < 4; kk++) mma16816(acc[nt], ah[kk], bl[kk]);
        }
        __syncthreads();
    }

    const int gm = m0 + wid * 16 + g;
#pragma unroll
    for (int nt = 0; nt < 8; nt++) {
        const int n = n0 + nt * 8 + tig * 2;
        if (MODE == 0) {
            const float bx = bias[n], by = bias[n + 1];
            *(float2*)(Cf + (size_t)gm * D_ + n) =
                make_float2(acc[nt][0] + bx, acc[nt][1] + by);
            *(float2*)(Cf + (size_t)(gm + 8) * D_ + n) =
                make_float2(acc[nt][2] + bx, acc[nt][3] + by);
        } else if (MODE == 1) {
            const int b = gm >> 12, t = gm & (T_ - 1);
            const int h = n >> 6, hd = n & 63;
            const size_t i0 = (((size_t)(b * H_ + h)) * T_ + t) * HD_ + hd;
            const size_t i1 = i0 + 8 * HD_;
            __nv_bfloat162 h0 = __floats2bfloat162_rn(acc[nt][0], acc[nt][1]);
            __nv_bfloat162 h1 = __floats2bfloat162_rn(acc[nt][2], acc[nt][3]);
            float2 f0 = __bfloat1622float2(h0);
            float2 f1 = __bfloat1622float2(h1);
            *(__nv_bfloat162*)(Ch + i0) = h0;
            *(__nv_bfloat162*)(Ch + i1) = h1;
            *(__nv_bfloat162*)(Cl + i0) = __floats2bfloat162_rn(acc[nt][0] - f0.x, acc[nt][1] - f0.y);
            *(__nv_bfloat162*)(Cl + i1) = __floats2bfloat162_rn(acc[nt][2] - f1.x, acc[nt][3] - f1.y);
        } else {   // MODE 2: transposed V planes [bh][hd][t]
            const int b = gm >> 12, t = gm & (T_ - 1);
            const int h = n >> 6, hd = n & 63;
            const size_t r0i = (((size_t)(b * H_ + h)) * HD_ + hd) * T_;
#pragma unroll
            for (int e = 0; e < 2; e++) {
                float v0 = acc[nt][e];
                float v1 = acc[nt][2 + e];
                __nv_bfloat16 h0 = __float2bfloat16(v0);
                __nv_bfloat16 h1 = __float2bfloat16(v1);
                const size_t ix = r0i + (size_t)e * T_ + t;
                Ch[ix]     = h0;
                Ch[ix + 8] = h1;
                Cl[ix]     = __float2bfloat16(v0 - __bfloat162float(h0));
                Cl[ix + 8] = __float2bfloat16(v1 - __bfloat162float(h1));
            }
        }
    }
}

// ===========================================================================
// Causal flash attention: cp.async double-buffered, V pre-transposed,
// S-phase restructured into 4 independent MMA chains (2 halves x split accum).
// ===========================================================================
#define BQ 128
#define BK 64
#define SBUF (4 * BK * KSTR)
#define FLASH_SMEM (2 * SBUF * 2)      // 73728 bytes

__global__ __launch_bounds__(256, 2) void flash_mma(
    const __nv_bfloat16* __restrict__ Qh, const __nv_bfloat16* __restrict__ Ql,
    const __nv_bfloat16* __restrict__ Kh, const __nv_bfloat16* __restrict__ Kl,
    const __nv_bfloat16* __restrict__ Vth, const __nv_bfloat16* __restrict__ Vtl,
    __nv_bfloat16* __restrict__ Ch, __nv_bfloat16* __restrict__ Cl)
{
    extern __shared__ __nv_bfloat16 sm[];
    const uint32_t sbase = (uint32_t)__cvta_generic_to_shared(sm);

    const int tid  = threadIdx.x;
    const int wid  = tid >> 5, lane = tid & 31;
    const int g    = lane >> 2, tig = lane & 3;
    const int bh   = blockIdx.y;
    const int q0   = (gridDim.x - 1 - blockIdx.x) * BQ;

    const size_t base = (size_t)bh * T_ * HD_;
    const __nv_bfloat16* Qhg = Qh + base;  const __nv_bfloat16* Qlg = Ql + base;
    const __nv_bfloat16* Khg = Kh + base;  const __nv_bfloat16* Klg = Kl + base;
    const __nv_bfloat16* Vhg = Vth + base; const __nv_bfloat16* Vlg = Vtl + base;

    // ---- Stage Q through buffer-0, extract A frags ----
    __nv_bfloat16 (*qsH)[KSTR] = (__nv_bfloat16(*)[KSTR])(sm);
    __nv_bfloat16 (*qsL)[KSTR] = (__nv_bfloat16(*)[KSTR])(sm + BK * KSTR);
    uint32_t qhf[4][4], qlf[4][4];
    const int cprow = tid >> 2;
    const int cpd0  = (tid & 3) * 16;
#pragma unroll
    for (int pb = 0; pb < 2; pb++) {
        if (pb) __syncthreads();
        {
            const __nv_bfloat16* s0 = Qhg + (size_t)(q0 + pb * 64 + cprow) * HD_ + cpd0;
            const __nv_bfloat16* s1 = Qlg + (size_t)(q0 + pb * 64 + cprow) * HD_ + cpd0;
            *(uint4*)&qsH[cprow][cpd0]     = *(const uint4*)(s0);
            *(uint4*)&qsH[cprow][cpd0 + 8] = *(const uint4*)(s0 + 8);
            *(uint4*)&qsL[cprow][cpd0]     = *(const uint4*)(s1);
            *(uint4*)&qsL[cprow][cpd0 + 8] = *(const uint4*)(s1 + 8);
        }
        __syncthreads();
        if ((wid >> 2) == pb) {
            const int r0 = (wid & 3) * 16 + g;
#pragma unroll
            for (int kt = 0; kt < 4; kt++) {
                const int c0 = kt * 16 + tig * 2;
                qhf[kt][0] = *(uint32_t*)&qsH[r0    ][c0    ];
                qhf[kt][1] = *(uint32_t*)&qsH[r0 + 8][c0    ];
                qhf[kt][2] = *(uint32_t*)&qsH[r0    ][c0 + 8];
                qhf[kt][3] = *(uint32_t*)&qsH[r0 + 8][c0 + 8];
                qlf[kt][0] = *(uint32_t*)&qsL[r0    ][c0    ];
                qlf[kt][1] = *(uint32_t*)&qsL[r0 + 8][c0    ];
                qlf[kt][2] = *(uint32_t*)&qsL[r0    ][c0 + 8];
                qlf[kt][3] = *(uint32_t*)&qsL[r0 + 8][c0 + 8];
            }
        }
    }
    __syncthreads();

    const int pr = tid >> 2;
    const int pe = (tid & 3) * 16;
    const __nv_bfloat16* kh_src = Khg + (size_t)pr * HD_ + pe;
    const __nv_bfloat16* kl_src = Klg + (size_t)pr * HD_ + pe;
    const __nv_bfloat16* vh_src = Vhg + (size_t)pr * T_ + pe;
    const __nv_bfloat16* vl_src = Vlg + (size_t)pr * T_ + pe;
    const uint32_t drow = sbase + (uint32_t)(pr * KSTR + pe) * 2;

    auto prefetch = [&](int jt, int b) {
        const int k0 = jt * BK;
        const uint32_t d0 = drow + (uint32_t)b * (SBUF * 2);
        const __nv_bfloat16* s;
        s = kh_src + (size_t)k0 * HD_;
        cpa16(d0, s); cpa16(d0 + 16, s + 8);
        s = kl_src + (size_t)k0 * HD_;
        cpa16(d0 + BK * KSTR * 2, s); cpa16(d0 + BK * KSTR * 2 + 16, s + 8);
        s = vh_src + k0;
        cpa16(d0 + 2 * BK * KSTR * 2, s); cpa16(d0 + 2 * BK * KSTR * 2 + 16, s + 8);
        s = vl_src + k0;
        cpa16(d0 + 3 * BK * KSTR * 2, s); cpa16(d0 + 3 * BK * KSTR * 2 + 16, s + 8);
    };

    float O[8][4];
#pragma unroll
    for (int i = 0; i < 8; i++)
#pragma unroll
        for (int j = 0; j < 4; j++) O[i][j] = 0.f;
    float l0 = 0.f, l1 = 0.f;

    const float SC = 0.18033688011112042f;
    const int r0g = q0 + wid * 16 + g;
    const int r1g = r0g + 8;
    const int ntiles = (q0 >> 6) + 2;

    prefetch(0, 0);
    CP_COMMIT();

    for (int jt = 0; jt < ntiles; jt++) {
        const int k0 = jt * BK;
        CP_WAIT0();
        __syncthreads();
        if (jt + 1 < ntiles) { prefetch(jt + 1, (jt + 1) & 1); CP_COMMIT(); }

        __nv_bfloat16 (*cKh)[KSTR] = (__nv_bfloat16(*)[KSTR])(sm + (jt & 1) * SBUF);
        __nv_bfloat16 (*cKl)[KSTR] = (__nv_bfloat16(*)[KSTR])(sm + (jt & 1) * SBUF + BK * KSTR);
        __nv_bfloat16 (*cVh)[KSTR] = (__nv_bfloat16(*)[KSTR])(sm + (jt & 1) * SBUF + 2 * BK * KSTR);
        __nv_bfloat16 (*cVl)[KSTR] = (__nv_bfloat16(*)[KSTR])(sm + (jt & 1) * SBUF + 3 * BK * KSTR);

        if (jt == ntiles - 1 && wid < 4) continue;
        const bool needmask = (jt >= ntiles - 2);

#pragma unroll
        for (int kt = 0; kt < 4; kt++) {
            // ---- S for both n-tile halves: 4 independent MMA chains ----
            float ca[2][4], cb[2][4];
#pragma unroll
            for (int hf = 0; hf < 2; hf++)
#pragma unroll
                for (int r = 0; r < 4; r++) { ca[hf][r] = 0.f; cb[hf][r] = 0.f; }

            uint32_t bf[2][4][2];
            const int row0 = (2 * kt) * 8 + g, row1 = (2 * kt + 1) * 8 + g;
#pragma unroll
            for (int kk = 0; kk < 4; kk++) {
                const int col = kk * 16 + tig * 2;
                bf[0][kk][0] = *(uint32_t*)&cKh[row0][col];
                bf[0][kk][1] = *(uint32_t*)&cKh[row0][col + 8];
                bf[1][kk][0] = *(uint32_t*)&cKh[row1][col];
                bf[1][kk][1] = *(uint32_t*)&cKh[row1][col + 8];
            }
#pragma unroll
            for (int kk = 0; kk < 4; kk++) {
                mma16816(ca[0], qhf[kk], bf[0][kk]);
                mma16816(ca[1], qhf[kk], bf[1][kk]);
            }
#pragma unroll
            for (int kk = 0; kk < 4; kk++) {
                mma16816(cb[0], qlf[kk], bf[0][kk]);
                mma16816(cb[1], qlf[kk], bf[1][kk]);
            }
#pragma unroll
            for (int kk = 0; kk < 4; kk++) {
                const int col = kk * 16 + tig * 2;
                bf[0][kk][0] = *(uint32_t*)&cKl[row0][col];
                bf[0][kk][1] = *(uint32_t*)&cKl[row0][col + 8];
                bf[1][kk][0] = *(uint32_t*)&cKl[row1][col];
                bf[1][kk][1] = *(uint32_t*)&cKl[row1][col + 8];
            }
#pragma unroll
            for (int kk = 0; kk < 4; kk++) {
                mma16816(cb[0], qhf[kk], bf[0][kk]);
                mma16816(cb[1], qhf[kk], bf[1][kk]);
            }

            // ---- Softmax both halves, pack P ----
            uint32_t pa_h[4], pa_l[4];
#pragma unroll
            for (int hf = 0; hf < 2; hf++) {
                const int kp = k0 + (2 * kt + hf) * 8 + tig * 2;
                float s0 = ca[hf][0] + cb[hf][0];
                float s1 = ca[hf][1] + cb[hf][1];
                float s2 = ca[hf][2] + cb[hf][2];
                float s3 = ca[hf][3] + cb[hf][3];
                float p00 = fexp2(s0 * SC), p01 = fexp2(s1 * SC);
                float p10 = fexp2(s2 * SC), p11 = fexp2(s3 * SC);
                if (needmask) {
                    if (kp     > r0g) p00 = 0.f;
                    if (kp + 1 > r0g) p01 = 0.f;
                    if (kp     > r1g) p10 = 0.f;
                    if (kp + 1 > r1g) p11 = 0.f;
                }
                l0 += p00 + p01;
                l1 += p10 + p11;
                uint32_t h0 = packbf(p00, p01), h1 = packbf(p10, p11);
                float2 f0 = __bfloat1622float2(*(__nv_bfloat162*)&h0);
                float2 f1 = __bfloat1622float2(*(__nv_bfloat162*)&h1);
                pa_h[hf * 2 + 0] = h0;
                pa_h[hf * 2 + 1] = h1;
                pa_l[hf * 2 + 0] = packbf(p00 - f0.x, p01 - f0.y);
                pa_l[hf * 2 + 1] = packbf(p10 - f1.x, p11 - f1.y);
            }

            // ---- PV: 8 independent chains of 3 ----
#pragma unroll
            for (int dn = 0; dn < 8; dn++) {
                const int d = dn * 8 + g;
                const int c0 = kt * 16 + tig * 2;
                uint32_t bv[2], bvl[2];
                bv[0]  = *(uint32_t*)&cVh[d][c0];
                bv[1]  = *(uint32_t*)&cVh[d][c0 + 8];
                bvl[0] = *(uint32_t*)&cVl[d][c0];
                bvl[1] = *(uint32_t*)&cVl[d][c0 + 8];
                mma16816(O[dn], pa_h, bv);
                mma16816(O[dn], pa_l, bv);
                mma16816(O[dn], pa_h, bvl);
            }
        }
    }

    l0 += __shfl_xor_sync(0xffffffffu, l0, 1);
    l0 += __shfl_xor_sync(0xffffffffu, l0, 2);
    l1 += __shfl_xor_sync(0xffffffffu, l1, 1);
    l1 += __shfl_xor_sync(0xffffffffu, l1, 2);
    const float i0 = 1.0f / l0, i1 = 1.0f / l1;

    const int b = bh >> 3, h = bh & 7;
    const size_t o0 = ((size_t)(b * T_ + r0g)) * D_ + h * HD_;
    const size_t o1 = ((size_t)(b * T_ + r1g)) * D_ + h * HD_;
#pragma unroll
    for (int dn = 0; dn < 8; dn++) {
        const int d = dn * 8 + tig * 2;
        float a0 = O[dn][0] * i0, a1 = O[dn][1] * i0;
        float b0 = O[dn][2] * i1, b1 = O[dn][3] * i1;
        __nv_bfloat162 h0 = __floats2bfloat162_rn(a0, a1);
        __nv_bfloat162 h1 = __floats2bfloat162_rn(b0, b1);
        float2 f0 = __bfloat1622float2(h0);
        float2 f1 = __bfloat1622float2(h1);
        *(__nv_bfloat162*)(Ch + o0 + d) = h0;
        *(__nv_bfloat162*)(Ch + o1 + d) = h1;
        *(__nv_bfloat162*)(Cl + o0 + d) = __floats2bfloat162_rn(a0 - f0.x, a1 - f0.y);
        *(__nv_bfloat162*)(Cl + o1 + d) = __floats2bfloat162_rn(b0 - f1.x, b1 - f1.y);
    }
}

// ===========================================================================
extern "C" void kernel_launch(void* const* d_in, const int* in_sizes, int n_in,
                              void* d_out, int out_size)
{
    const float* x  = (const float*)d_in[0];
    const float* Wq = (const float*)d_in[1];
    const float* Wk = (const float*)d_in[2];
    const float* Wv = (const float*)d_in[3];
    const float* Wo = (const float*)d_in[4];
    const float* bo = (const float*)d_in[5];
    float* out = (float*)d_out;

    __nv_bfloat16 *qh, *ql, *kh, *kl, *vth, *vtl, *ch, *cl, *xh, *xl, *wh, *wl;
    cudaGetSymbolAddress((void**)&qh, g_qh); cudaGetSymbolAddress((void**)&ql, g_ql);
    cudaGetSymbolAddress((void**)&kh, g_kh); cudaGetSymbolAddress((void**)&kl, g_kl);
    cudaGetSymbolAddress((void**)&vth, g_vth); cudaGetSymbolAddress((void**)&vtl, g_vtl);
    cudaGetSymbolAddress((void**)&ch, g_ch); cudaGetSymbolAddress((void**)&cl, g_cl);
    cudaGetSymbolAddress((void**)&xh, g_xh); cudaGetSymbolAddress((void**)&xl, g_xl);
    cudaGetSymbolAddress((void**)&wh, g_wh); cudaGetSymbolAddress((void**)&wl, g_wl);

    static bool attr_done = false;
    if (!attr_done) {
        cudaFuncSetAttribute(gemm_hmma<0>, cudaFuncAttributeMaxDynamicSharedMemorySize, GEMM_SMEM);
        cudaFuncSetAttribute(gemm_hmma<1>, cudaFuncAttributeMaxDynamicSharedMemorySize, GEMM_SMEM);
        cudaFuncSetAttribute(gemm_hmma<2>, cudaFuncAttributeMaxDynamicSharedMemorySize, GEMM_SMEM);
        cudaFuncSetAttribute(flash_mma, cudaFuncAttributeMaxDynamicSharedMemorySize, FLASH_SMEM);
        attr_done = true;
    }

    split_f32<<<(M_ * D_ / 4 + 255) / 256, 256>>>(x,  xh, xl, M_ * D_ / 4);
    split_f32<<<(D_ * D_ / 4 + 255) / 256, 256>>>(Wq, wh + 0 * (size_t)D_ * D_, wl + 0 * (size_t)D_ * D_, D_ * D_ / 4);
    split_f32<<<(D_ * D_ / 4 + 255) / 256, 256>>>(Wk, wh + 1 * (size_t)D_ * D_, wl + 1 * (size_t)D_ * D_, D_ * D_ / 4);
    split_f32<<<(D_ * D_ / 4 + 255) / 256, 256>>>(Wv, wh + 2 * (size_t)D_ * D_, wl + 2 * (size_t)D_ * D_, D_ * D_ / 4);
    split_f32<<<(D_ * D_ / 4 + 255) / 256, 256>>>(Wo, wh + 3 * (size_t)D_ * D_, wl + 3 * (size_t)D_ * D_, D_ * D_ / 4);

    dim3 ggrid(D_ / 64, M_ / 128);   // (8, 64)

    gemm_hmma<1><<<ggrid, 256, GEMM_SMEM>>>(xh, xl, wh + 0 * (size_t)D_ * D_, wl + 0 * (size_t)D_ * D_,
                                            nullptr, nullptr, qh, ql);
    gemm_hmma<1><<<ggrid, 256, GEMM_SMEM>>>(xh, xl, wh + 1 * (size_t)D_ * D_, wl + 1 * (size_t)D_ * D_,
                                            nullptr, nullptr, kh, kl);
    gemm_hmma<2><<<ggrid, 256, GEMM_SMEM>>>(xh, xl, wh + 2 * (size_t)D_ * D_, wl + 2 * (size_t)D_ * D_,
                                            nullptr, nullptr, vth, vtl);

    dim3 agrid(T_ / BQ, B_ * H_);    // (32, 16)
    flash_mma<<<agrid, 256, FLASH_SMEM>>>(qh, ql, kh, kl, vth, vtl, ch, cl);

    gemm_hmma<0><<<ggrid, 256, GEMM_SMEM>>>(ch, cl, wh + 3 * (size_t)D_ * D_, wl + 3 * (size_t)D_ * D_,
                                            bo, out, nullptr, nullptr);
}

// round 13
// speedup vs baseline: 1.1191x; 1.0887x over previous
#include <cuda_runtime.h>
#include <cuda_bf16.h>
#include <cstdint>

#define B_  2
#define T_  4096
#define D_  512
#define H_  8
#define HD_ 64
#define M_  (B_*T_)
#define KSTR 72   // smem row stride (bf16): 144B, conflict-free frag loads

// Scratch planes (allocation-free)
__device__ __nv_bfloat16 g_qh[B_*T_*D_], g_ql[B_*T_*D_];
__device__ __nv_bfloat16 g_kh[B_*T_*D_];                     // K hi only (lo dropped)
__device__ __nv_bfloat16 g_vth[B_*T_*D_], g_vtl[B_*T_*D_];   // V hi+lo, transposed [bh][hd][T]
__device__ __nv_bfloat16 g_ch[B_*T_*D_], g_cl[B_*T_*D_];     // ctx planes
__device__ __nv_bfloat16 g_xh[M_*D_],    g_xl[M_*D_];        // token_embed planes
__device__ __nv_bfloat16 g_wh[4][D_*D_], g_wl[4][D_*D_];     // Wq,Wk,Wv,Wo planes

// ---------------------------------------------------------------------------
__device__ __forceinline__ void mma16816(float* c, const uint32_t* a, const uint32_t* b) {
    asm volatile(
        "mma.sync.aligned.m16n8k16.row.col.f32.bf16.bf16.f32 "
        "{%0,%1,%2,%3}, {%4,%5,%6,%7}, {%8,%9}, {%0,%1,%2,%3};"
        : "+f"(c[0]), "+f"(c[1]), "+f"(c[2]), "+f"(c[3])
        : "r"(a[0]), "r"(a[1]), "r"(a[2]), "r"(a[3]), "r"(b[0]), "r"(b[1]));
}

__device__ __forceinline__ void cpa16(uint32_t dst, const void* src) {
    asm volatile("cp.async.cg.shared.global [%0], [%1], 16;" :: "r"(dst), "l"(src));
}
#define CP_COMMIT() asm volatile("cp.async.commit_group;" ::: "memory")
#define CP_WAIT0()  asm volatile("cp.async.wait_group 0;" ::: "memory")

__device__ __forceinline__ float fexp2(float x) {
    float t = x + 12582912.0f;
    int   n = __float_as_int(t) - __float_as_int(12582912.0f);
    float f = x - (t - 12582912.0f);
    float p = 1.3333558146e-3f;
    p = fmaf(p, f, 9.6181291076e-3f);
    p = fmaf(p, f, 5.5504108664e-2f);
    p = fmaf(p, f, 2.4022650696e-1f);
    p = fmaf(p, f, 6.9314718056e-1f);
    p = fmaf(p, f, 1.0f);
    return p * __int_as_float((n + 127) << 23);
}

__device__ __forceinline__ uint32_t packbf(float a, float b) {
    __nv_bfloat162 h = __floats2bfloat162_rn(a, b);
    return *(uint32_t*)&h;
}

// ---------------------------------------------------------------------------
__global__ __launch_bounds__(256) void split_f32(
    const float* __restrict__ in, __nv_bfloat16* __restrict__ hi,
    __nv_bfloat16* __restrict__ lo, int n4)
{
    const int i = blockIdx.x * blockDim.x + threadIdx.x;
    if (i >= n4) return;
    float4 x = ((const float4*)in)[i];
    __nv_bfloat162 h0 = __floats2bfloat162_rn(x.x, x.y);
    __nv_bfloat162 h1 = __floats2bfloat162_rn(x.z, x.w);
    float2 f0 = __bfloat1622float2(h0);
    float2 f1 = __bfloat1622float2(h1);
    ((__nv_bfloat162*)hi)[2*i]     = h0;
    ((__nv_bfloat162*)hi)[2*i + 1] = h1;
    ((__nv_bfloat162*)lo)[2*i]     = __floats2bfloat162_rn(x.x - f0.x, x.y - f0.y);
    ((__nv_bfloat162*)lo)[2*i + 1] = __floats2bfloat162_rn(x.z - f1.x, x.w - f1.y);
}

// ===========================================================================
// Split-bf16 HMMA GEMM (3-term), cp.async double-buffered.
// MODE 0: fp32 out + bias. MODE 1: head layout hi+lo (Q).
// MODE 2: transposed head layout [bh][hd][t], hi+lo (V).
// MODE 3: head layout hi only (K).
// ===========================================================================
#define GBUF (384 * KSTR)
#define GEMM_SMEM (2 * GBUF * 2)       // 110592 bytes

template <int MODE>
__global__ __launch_bounds__(256, 2) void gemm_hmma(
    const __nv_bfloat16* __restrict__ Ah, const __nv_bfloat16* __restrict__ Al,
    const __nv_bfloat16* __restrict__ Wh, const __nv_bfloat16* __restrict__ Wl,
    const float* __restrict__ bias, float* __restrict__ Cf,
    __nv_bfloat16* __restrict__ Ch, __nv_bfloat16* __restrict__ Cl)
{
    extern __shared__ __nv_bfloat16 sm[];
    const uint32_t sbase = (uint32_t)__cvta_generic_to_shared(sm);

    const int tid = threadIdx.x, wid = tid >> 5, lane = tid & 31;
    const int g = lane >> 2, tig = lane & 3;
    const int m0 = blockIdx.y * 128, n0 = blockIdx.x * 64;

    const int ar = tid >> 1, ad0 = (tid & 1) * 32;
    const int wr = tid >> 2, wd0 = (tid & 3) * 16;

    const __nv_bfloat16* pa_src = Ah + (size_t)(m0 + ar) * D_ + ad0;
    const __nv_bfloat16* pl_src = Al + (size_t)(m0 + ar) * D_ + ad0;
    const __nv_bfloat16* pw_src = Wh + (size_t)(n0 + wr) * D_ + wd0;
    const __nv_bfloat16* pq_src = Wl + (size_t)(n0 + wr) * D_ + wd0;
    const uint32_t da = sbase + (uint32_t)(ar * KSTR + ad0) * 2;
    const uint32_t dw = sbase + (uint32_t)(256 * KSTR + wr * KSTR + wd0) * 2;

    auto prefetch = [&](int k0, int b) {
        const uint32_t off = (uint32_t)b * (GBUF * 2);
        const __nv_bfloat16* s;
        s = pa_src + k0;
#pragma unroll
        for (int u = 0; u < 4; u++) cpa16(da + off + u * 16, s + u * 8);
        s = pl_src + k0;
#pragma unroll
        for (int u = 0; u < 4; u++) cpa16(da + off + 128 * KSTR * 2 + u * 16, s + u * 8);
        s = pw_src + k0;
#pragma unroll
        for (int u = 0; u < 2; u++) cpa16(dw + off + u * 16, s + u * 8);
        s = pq_src + k0;
#pragma unroll
        for (int u = 0; u < 2; u++) cpa16(dw + off + 64 * KSTR * 2 + u * 16, s + u * 8);
    };

    float acc[8][4];
#pragma unroll
    for (int i = 0; i < 8; i++)
#pragma unroll
        for (int j = 0; j < 4; j++) acc[i][j] = 0.f;

    prefetch(0, 0);
    CP_COMMIT();

    for (int it = 0; it < 8; it++) {
        CP_WAIT0();
        __syncthreads();
        if (it + 1 < 8) { prefetch((it + 1) * 64, (it + 1) & 1); CP_COMMIT(); }

        const __nv_bfloat16* buf = sm + (it & 1) * GBUF;
        __nv_bfloat16 (*sAh)[KSTR] = (__nv_bfloat16(*)[KSTR])(buf);
        __nv_bfloat16 (*sAl)[KSTR] = (__nv_bfloat16(*)[KSTR])(buf + 128 * KSTR);
        __nv_bfloat16 (*sWh)[KSTR] = (__nv_bfloat16(*)[KSTR])(buf + 256 * KSTR);
        __nv_bfloat16 (*sWl)[KSTR] = (__nv_bfloat16(*)[KSTR])(buf + 320 * KSTR);

        uint32_t ah[4][4], al[4][4];
        const int r0 = wid * 16 + g;
#pragma unroll
        for (int kt = 0; kt < 4; kt++) {
            const int c0 = kt * 16 + tig * 2;
            ah[kt][0] = *(uint32_t*)&sAh[r0    ][c0    ];
            ah[kt][1] = *(uint32_t*)&sAh[r0 + 8][c0    ];
            ah[kt][2] = *(uint32_t*)&sAh[r0    ][c0 + 8];
            ah[kt][3] = *(uint32_t*)&sAh[r0 + 8][c0 + 8];
            al[kt][0] = *(uint32_t*)&sAl[r0    ][c0    ];
            al[kt][1] = *(uint32_t*)&sAl[r0 + 8][c0    ];
            al[kt][2] = *(uint32_t*)&sAl[r0    ][c0 + 8];
            al[kt][3] = *(uint32_t*)&sAl[r0 + 8][c0 + 8];
        }
#pragma unroll
        for (int nt = 0; nt < 8; nt++) {
            const int row = nt * 8 + g;
            uint32_t bh[4][2], bl[4][2];
#pragma unroll
            for (int kk = 0; kk < 4; kk++) {
                const int c = kk * 16 + tig * 2;
                bh[kk][0] = *(uint32_t*)&sWh[row][c];
                bh[kk][1] = *(uint32_t*)&sWh[row][c + 8];
                bl[kk][0] = *(uint32_t*)&sWl[row][c];
                bl[kk][1] = *(uint32_t*)&sWl[row][c + 8];
            }
#pragma unroll
            for (int kk = 0; kk < 4; kk++) mma16816(acc[nt], ah[kk], bh[kk]);
#pragma unroll
            for (int kk = 0; kk < 4; kk++) mma16816(acc[nt], al[kk], bh[kk]);
#pragma unroll
            for (int kk = 0; kk < 4; kk++) mma16816(acc[nt], ah[kk], bl[kk]);
        }
        __syncthreads();
    }

    const int gm = m0 + wid * 16 + g;
#pragma unroll
    for (int nt = 0; nt < 8; nt++) {
        const int n = n0 + nt * 8 + tig * 2;
        if (MODE == 0) {
            const float bx = bias[n], by = bias[n + 1];
            *(float2*)(Cf + (size_t)gm * D_ + n) =
                make_float2(acc[nt][0] + bx, acc[nt][1] + by);
            *(float2*)(Cf + (size_t)(gm + 8) * D_ + n) =
                make_float2(acc[nt][2] + bx, acc[nt][3] + by);
        } else if (MODE == 1 || MODE == 3) {
            const int b = gm >> 12, t = gm & (T_ - 1);
            const int h = n >> 6, hd = n & 63;
            const size_t i0 = (((size_t)(b * H_ + h)) * T_ + t) * HD_ + hd;
            const size_t i1 = i0 + 8 * HD_;
            __nv_bfloat162 h0 = __floats2bfloat162_rn(acc[nt][0], acc[nt][1]);
            __nv_bfloat162 h1 = __floats2bfloat162_rn(acc[nt][2], acc[nt][3]);
            *(__nv_bfloat162*)(Ch + i0) = h0;
            *(__nv_bfloat162*)(Ch + i1) = h1;
            if (MODE == 1) {
                float2 f0 = __bfloat1622float2(h0);
                float2 f1 = __bfloat1622float2(h1);
                *(__nv_bfloat162*)(Cl + i0) = __floats2bfloat162_rn(acc[nt][0] - f0.x, acc[nt][1] - f0.y);
                *(__nv_bfloat162*)(Cl + i1) = __floats2bfloat162_rn(acc[nt][2] - f1.x, acc[nt][3] - f1.y);
            }
        } else {   // MODE 2: transposed V hi+lo planes [bh][hd][t]
            const int b = gm >> 12, t = gm & (T_ - 1);
            const int h = n >> 6, hd = n & 63;
            const size_t r0i = (((size_t)(b * H_ + h)) * HD_ + hd) * T_;
#pragma unroll
            for (int e = 0; e < 2; e++) {
                float v0 = acc[nt][e];
                float v1 = acc[nt][2 + e];
                __nv_bfloat16 h0 = __float2bfloat16(v0);
                __nv_bfloat16 h1 = __float2bfloat16(v1);
                const size_t ix = r0i + (size_t)e * T_ + t;
                Ch[ix]     = h0;
                Ch[ix + 8] = h1;
                Cl[ix]     = __float2bfloat16(v0 - __bfloat162float(h0));
                Cl[ix + 8] = __float2bfloat16(v1 - __bfloat162float(h1));
            }
        }
    }
}

// ===========================================================================
// Causal flash attention, rebalanced precision:
//   S = (qh + ql) . kh              (K lo dropped: err ~4e-4, cancels in softmax)
//   O = (ph + pl) . vh + ph . vl    (full 3-term PV: V lo essential)
// cp.async double-buffered Kh/Vh/Vl tiles (V pre-transposed globally).
// ===========================================================================
#define BQ 128
#define BK 64
#define SBUF (3 * BK * KSTR)           // Kh + Vh + Vl per stage
#define FLASH_SMEM (2 * SBUF * 2)      // 55296 bytes

__global__ __launch_bounds__(256, 2) void flash_mma(
    const __nv_bfloat16* __restrict__ Qh, const __nv_bfloat16* __restrict__ Ql,
    const __nv_bfloat16* __restrict__ Kh,
    const __nv_bfloat16* __restrict__ Vth, const __nv_bfloat16* __restrict__ Vtl,
    __nv_bfloat16* __restrict__ Ch, __nv_bfloat16* __restrict__ Cl)
{
    extern __shared__ __nv_bfloat16 sm[];
    const uint32_t sbase = (uint32_t)__cvta_generic_to_shared(sm);

    const int tid  = threadIdx.x;
    const int wid  = tid >> 5, lane = tid & 31;
    const int g    = lane >> 2, tig = lane & 3;
    const int bh   = blockIdx.y;
    const int q0   = (gridDim.x - 1 - blockIdx.x) * BQ;

    const size_t base = (size_t)bh * T_ * HD_;
    const __nv_bfloat16* Qhg = Qh + base; const __nv_bfloat16* Qlg = Ql + base;
    const __nv_bfloat16* Khg = Kh + base;
    const __nv_bfloat16* Vhg = Vth + base; const __nv_bfloat16* Vlg = Vtl + base;

    // ---- Stage Q through buffer-0, extract A frags ----
    __nv_bfloat16 (*qsH)[KSTR] = (__nv_bfloat16(*)[KSTR])(sm);
    __nv_bfloat16 (*qsL)[KSTR] = (__nv_bfloat16(*)[KSTR])(sm + BK * KSTR);
    uint32_t qhf[4][4], qlf[4][4];
    const int cprow = tid >> 2;
    const int cpd0  = (tid & 3) * 16;
#pragma unroll
    for (int pb = 0; pb < 2; pb++) {
        if (pb) __syncthreads();
        {
            const __nv_bfloat16* s0 = Qhg + (size_t)(q0 + pb * 64 + cprow) * HD_ + cpd0;
            const __nv_bfloat16* s1 = Qlg + (size_t)(q0 + pb * 64 + cprow) * HD_ + cpd0;
            *(uint4*)&qsH[cprow][cpd0]     = *(const uint4*)(s0);
            *(uint4*)&qsH[cprow][cpd0 + 8] = *(const uint4*)(s0 + 8);
            *(uint4*)&qsL[cprow][cpd0]     = *(const uint4*)(s1);
            *(uint4*)&qsL[cprow][cpd0 + 8] = *(const uint4*)(s1 + 8);
        }
        __syncthreads();
        if ((wid >> 2) == pb) {
            const int r0 = (wid & 3) * 16 + g;
#pragma unroll
            for (int kt = 0; kt < 4; kt++) {
                const int c0 = kt * 16 + tig * 2;
                qhf[kt][0] = *(uint32_t*)&qsH[r0    ][c0    ];
                qhf[kt][1] = *(uint32_t*)&qsH[r0 + 8][c0    ];
                qhf[kt][2] = *(uint32_t*)&qsH[r0    ][c0 + 8];
                qhf[kt][3] = *(uint32_t*)&qsH[r0 + 8][c0 + 8];
                qlf[kt][0] = *(uint32_t*)&qsL[r0    ][c0    ];
                qlf[kt][1] = *(uint32_t*)&qsL[r0 + 8][c0    ];
                qlf[kt][2] = *(uint32_t*)&qsL[r0    ][c0 + 8];
                qlf[kt][3] = *(uint32_t*)&qsL[r0 + 8][c0 + 8];
            }
        }
    }
    __syncthreads();

    const int pr = tid >> 2;
    const int pe = (tid & 3) * 16;
    const __nv_bfloat16* kh_src = Khg + (size_t)pr * HD_ + pe;
    const __nv_bfloat16* vh_src = Vhg + (size_t)pr * T_ + pe;
    const __nv_bfloat16* vl_src = Vlg + (size_t)pr * T_ + pe;
    const uint32_t drow = sbase + (uint32_t)(pr * KSTR + pe) * 2;

    auto prefetch = [&](int jt, int b) {
        const int k0 = jt * BK;
        const uint32_t d0 = drow + (uint32_t)b * (SBUF * 2);
        const __nv_bfloat16* s;
        s = kh_src + (size_t)k0 * HD_;
        cpa16(d0, s); cpa16(d0 + 16, s + 8);
        s = vh_src + k0;
        cpa16(d0 + BK * KSTR * 2, s); cpa16(d0 + BK * KSTR * 2 + 16, s + 8);
        s = vl_src + k0;
        cpa16(d0 + 2 * BK * KSTR * 2, s); cpa16(d0 + 2 * BK * KSTR * 2 + 16, s + 8);
    };

    float O[8][4];
#pragma unroll
    for (int i = 0; i < 8; i++)
#pragma unroll
        for (int j = 0; j < 4; j++) O[i][j] = 0.f;
    float l0 = 0.f, l1 = 0.f;

    const float SC = 0.18033688011112042f;
    const int r0g = q0 + wid * 16 + g;
    const int r1g = r0g + 8;
    const int ntiles = (q0 >> 6) + 2;

    prefetch(0, 0);
    CP_COMMIT();

    for (int jt = 0; jt < ntiles; jt++) {
        const int k0 = jt * BK;
        CP_WAIT0();
        __syncthreads();
        if (jt + 1 < ntiles) { prefetch(jt + 1, (jt + 1) & 1); CP_COMMIT(); }

        __nv_bfloat16 (*cKh)[KSTR] = (__nv_bfloat16(*)[KSTR])(sm + (jt & 1) * SBUF);
        __nv_bfloat16 (*cVh)[KSTR] = (__nv_bfloat16(*)[KSTR])(sm + (jt & 1) * SBUF + BK * KSTR);
        __nv_bfloat16 (*cVl)[KSTR] = (__nv_bfloat16(*)[KSTR])(sm + (jt & 1) * SBUF + 2 * BK * KSTR);

        if (jt == ntiles - 1 && wid < 4) continue;
        const bool needmask = (jt >= ntiles - 2);

#pragma unroll
        for (int kt = 0; kt < 4; kt++) {
            // ---- S both halves: 4 independent chains (qh.kh, ql.kh per half)
            float ca[2][4], cb[2][4];
#pragma unroll
            for (int hf = 0; hf < 2; hf++)
#pragma unroll
                for (int r = 0; r < 4; r++) { ca[hf][r] = 0.f; cb[hf][r] = 0.f; }

            uint32_t bf[2][4][2];
            const int row0 = (2 * kt) * 8 + g, row1 = (2 * kt + 1) * 8 + g;
#pragma unroll
            for (int kk = 0; kk < 4; kk++) {
                const int col = kk * 16 + tig * 2;
                bf[0][kk][0] = *(uint32_t*)&cKh[row0][col];
                bf[0][kk][1] = *(uint32_t*)&cKh[row0][col + 8];
                bf[1][kk][0] = *(uint32_t*)&cKh[row1][col];
                bf[1][kk][1] = *(uint32_t*)&cKh[row1][col + 8];
            }
#pragma unroll
            for (int kk = 0; kk < 4; kk++) {
                mma16816(ca[0], qhf[kk], bf[0][kk]);
                mma16816(ca[1], qhf[kk], bf[1][kk]);
            }
#pragma unroll
            for (int kk = 0; kk < 4; kk++) {
                mma16816(cb[0], qlf[kk], bf[0][kk]);
                mma16816(cb[1], qlf[kk], bf[1][kk]);
            }

            // ---- Softmax both halves, pack P hi/lo ----
            uint32_t pa_h[4], pa_l[4];
#pragma unroll
            for (int hf = 0; hf < 2; hf++) {
                const int kp = k0 + (2 * kt + hf) * 8 + tig * 2;
                float s0 = ca[hf][0] + cb[hf][0];
                float s1 = ca[hf][1] + cb[hf][1];
                float s2 = ca[hf][2] + cb[hf][2];
                float s3 = ca[hf][3] + cb[hf][3];
                float p00 = fexp2(s0 * SC), p01 = fexp2(s1 * SC);
                float p10 = fexp2(s2 * SC), p11 = fexp2(s3 * SC);
                if (needmask) {
                    if (kp     > r0g) p00 = 0.f;
                    if (kp + 1 > r0g) p01 = 0.f;
                    if (kp     > r1g) p10 = 0.f;
                    if (kp + 1 > r1g) p11 = 0.f;
                }
                l0 += p00 + p01;
                l1 += p10 + p11;
                uint32_t h0 = packbf(p00, p01), h1 = packbf(p10, p11);
                float2 f0 = __bfloat1622float2(*(__nv_bfloat162*)&h0);
                float2 f1 = __bfloat1622float2(*(__nv_bfloat162*)&h1);
                pa_h[hf * 2 + 0] = h0;
                pa_h[hf * 2 + 1] = h1;
                pa_l[hf * 2 + 0] = packbf(p00 - f0.x, p01 - f0.y);
                pa_l[hf * 2 + 1] = packbf(p10 - f1.x, p11 - f1.y);
            }

            // ---- PV: ph.vh + pl.vh + ph.vl (3 MMAs per dn) ----
#pragma unroll
            for (int dn = 0; dn < 8; dn++) {
                const int d = dn * 8 + g;
                const int c0 = kt * 16 + tig * 2;
                uint32_t bv[2], bvl[2];
                bv[0]  = *(uint32_t*)&cVh[d][c0];
                bv[1]  = *(uint32_t*)&cVh[d][c0 + 8];
                bvl[0] = *(uint32_t*)&cVl[d][c0];
                bvl[1] = *(uint32_t*)&cVl[d][c0 + 8];
                mma16816(O[dn], pa_h, bv);
                mma16816(O[dn], pa_l, bv);
                mma16816(O[dn], pa_h, bvl);
            }
        }
    }

    l0 += __shfl_xor_sync(0xffffffffu, l0, 1);
    l0 += __shfl_xor_sync(0xffffffffu, l0, 2);
    l1 += __shfl_xor_sync(0xffffffffu, l1, 1);
    l1 += __shfl_xor_sync(0xffffffffu, l1, 2);
    const float i0 = 1.0f / l0, i1 = 1.0f / l1;

    const int b = bh >> 3, h = bh & 7;
    const size_t o0 = ((size_t)(b * T_ + r0g)) * D_ + h * HD_;
    const size_t o1 = ((size_t)(b * T_ + r1g)) * D_ + h * HD_;
#pragma unroll
    for (int dn = 0; dn < 8; dn++) {
        const int d = dn * 8 + tig * 2;
        float a0 = O[dn][0] * i0, a1 = O[dn][1] * i0;
        float b0 = O[dn][2] * i1, b1 = O[dn][3] * i1;
        __nv_bfloat162 h0 = __floats2bfloat162_rn(a0, a1);
        __nv_bfloat162 h1 = __floats2bfloat162_rn(b0, b1);
        float2 f0 = __bfloat1622float2(h0);
        float2 f1 = __bfloat1622float2(h1);
        *(__nv_bfloat162*)(Ch + o0 + d) = h0;
        *(__nv_bfloat162*)(Ch + o1 + d) = h1;
        *(__nv_bfloat162*)(Cl + o0 + d) = __floats2bfloat162_rn(a0 - f0.x, a1 - f0.y);
        *(__nv_bfloat162*)(Cl + o1 + d) = __floats2bfloat162_rn(b0 - f1.x, b1 - f1.y);
    }
}

// ===========================================================================
extern "C" void kernel_launch(void* const* d_in, const int* in_sizes, int n_in,
                              void* d_out, int out_size)
{
    const float* x  = (const float*)d_in[0];
    const float* Wq = (const float*)d_in[1];
    const float* Wk = (const float*)d_in[2];
    const float* Wv = (const float*)d_in[3];
    const float* Wo = (const float*)d_in[4];
    const float* bo = (const float*)d_in[5];
    float* out = (float*)d_out;

    __nv_bfloat16 *qh, *ql, *kh, *vth, *vtl, *ch, *cl, *xh, *xl, *wh, *wl;
    cudaGetSymbolAddress((void**)&qh, g_qh); cudaGetSymbolAddress((void**)&ql, g_ql);
    cudaGetSymbolAddress((void**)&kh, g_kh);
    cudaGetSymbolAddress((void**)&vth, g_vth); cudaGetSymbolAddress((void**)&vtl, g_vtl);
    cudaGetSymbolAddress((void**)&ch, g_ch); cudaGetSymbolAddress((void**)&cl, g_cl);
    cudaGetSymbolAddress((void**)&xh, g_xh); cudaGetSymbolAddress((void**)&xl, g_xl);
    cudaGetSymbolAddress((void**)&wh, g_wh); cudaGetSymbolAddress((void**)&wl, g_wl);

    static bool attr_done = false;
    if (!attr_done) {
        cudaFuncSetAttribute(gemm_hmma<0>, cudaFuncAttributeMaxDynamicSharedMemorySize, GEMM_SMEM);
        cudaFuncSetAttribute(gemm_hmma<1>, cudaFuncAttributeMaxDynamicSharedMemorySize, GEMM_SMEM);
        cudaFuncSetAttribute(gemm_hmma<2>, cudaFuncAttributeMaxDynamicSharedMemorySize, GEMM_SMEM);
        cudaFuncSetAttribute(gemm_hmma<3>, cudaFuncAttributeMaxDynamicSharedMemorySize, GEMM_SMEM);
        cudaFuncSetAttribute(flash_mma, cudaFuncAttributeMaxDynamicSharedMemorySize, FLASH_SMEM);
        attr_done = true;
    }

    split_f32<<<(M_ * D_ / 4 + 255) / 256, 256>>>(x,  xh, xl, M_ * D_ / 4);
    split_f32<<<(D_ * D_ / 4 + 255) / 256, 256>>>(Wq, wh + 0 * (size_t)D_ * D_, wl + 0 * (size_t)D_ * D_, D_ * D_ / 4);
    split_f32<<<(D_ * D_ / 4 + 255) / 256, 256>>>(Wk, wh + 1 * (size_t)D_ * D_, wl + 1 * (size_t)D_ * D_, D_ * D_ / 4);
    split_f32<<<(D_ * D_ / 4 + 255) / 256, 256>>>(Wv, wh + 2 * (size_t)D_ * D_, wl + 2 * (size_t)D_ * D_, D_ * D_ / 4);
    split_f32<<<(D_ * D_ / 4 + 255) / 256, 256>>>(Wo, wh + 3 * (size_t)D_ * D_, wl + 3 * (size_t)D_ * D_, D_ * D_ / 4);

    dim3 ggrid(D_ / 64, M_ / 128);   // (8, 64)

    gemm_hmma<1><<<ggrid, 256, GEMM_SMEM>>>(xh, xl, wh + 0 * (size_t)D_ * D_, wl + 0 * (size_t)D_ * D_,
                                            nullptr, nullptr, qh, ql);
    gemm_hmma<3><<<ggrid, 256, GEMM_SMEM>>>(xh, xl, wh + 1 * (size_t)D_ * D_, wl + 1 * (size_t)D_ * D_,
                                            nullptr, nullptr, kh, nullptr);
    gemm_hmma<2><<<ggrid, 256, GEMM_SMEM>>>(xh, xl, wh + 2 * (size_t)D_ * D_, wl + 2 * (size_t)D_ * D_,
                                            nullptr, nullptr, vth, vtl);

    dim3 agrid(T_ / BQ, B_ * H_);    // (32, 16)
    flash_mma<<<agrid, 256, FLASH_SMEM>>>(qh, ql, kh, vth, vtl, ch, cl);

    gemm_hmma<0><<<ggrid, 256, GEMM_SMEM>>>(ch, cl, wh + 3 * (size_t)D_ * D_, wl + 3 * (size_t)D_ * D_,
                                            bo, out, nullptr, nullptr);
}

// round 14
// speedup vs baseline: 1.6190x; 1.4467x over previous
#include <cuda_runtime.h>
#include <cuda_bf16.h>
#include <cuda_fp16.h>
#include <cstdint>

#define B_  2
#define T_  4096
#define D_  512
#define H_  8
#define HD_ 64
#define M_  (B_*T_)
#define KSTR 72   // smem row stride (elems): conflict-free frag loads

// Scratch (allocation-free)
__device__ __half g_qf[B_*T_*D_];                     // Q fp16, head layout [bh][t][hd]
__device__ __half g_kf[B_*T_*D_];                     // K fp16, head layout
__device__ __half g_vtf[B_*T_*D_];                    // V fp16, transposed [bh][hd][T]
__device__ __nv_bfloat16 g_ch[B_*T_*D_], g_cl[B_*T_*D_];   // ctx planes (bf16 hi/lo)
__device__ __nv_bfloat16 g_xh[M_*D_],    g_xl[M_*D_];      // token_embed planes
__device__ __nv_bfloat16 g_wh[4][D_*D_], g_wl[4][D_*D_];   // Wq,Wk,Wv,Wo planes

// ---------------------------------------------------------------------------
__device__ __forceinline__ void mma16816(float* c, const uint32_t* a, const uint32_t* b) {
    asm volatile(
        "mma.sync.aligned.m16n8k16.row.col.f32.bf16.bf16.f32 "
        "{%0,%1,%2,%3}, {%4,%5,%6,%7}, {%8,%9}, {%0,%1,%2,%3};"
        : "+f"(c[0]), "+f"(c[1]), "+f"(c[2]), "+f"(c[3])
        : "r"(a[0]), "r"(a[1]), "r"(a[2]), "r"(a[3]), "r"(b[0]), "r"(b[1]));
}
__device__ __forceinline__ void mma16816h(float* c, const uint32_t* a, const uint32_t* b) {
    asm volatile(
        "mma.sync.aligned.m16n8k16.row.col.f32.f16.f16.f32 "
        "{%0,%1,%2,%3}, {%4,%5,%6,%7}, {%8,%9}, {%0,%1,%2,%3};"
        : "+f"(c[0]), "+f"(c[1]), "+f"(c[2]), "+f"(c[3])
        : "r"(a[0]), "r"(a[1]), "r"(a[2]), "r"(a[3]), "r"(b[0]), "r"(b[1]));
}

__device__ __forceinline__ void cpa16(uint32_t dst, const void* src) {
    asm volatile("cp.async.cg.shared.global [%0], [%1], 16;" :: "r"(dst), "l"(src));
}
#define CP_COMMIT() asm volatile("cp.async.commit_group;" ::: "memory")
#define CP_WAIT0()  asm volatile("cp.async.wait_group 0;" ::: "memory")

__device__ __forceinline__ float fexp2(float x) {
    float t = x + 12582912.0f;
    int   n = __float_as_int(t) - __float_as_int(12582912.0f);
    float f = x - (t - 12582912.0f);
    float p = 1.3333558146e-3f;
    p = fmaf(p, f, 9.6181291076e-3f);
    p = fmaf(p, f, 5.5504108664e-2f);
    p = fmaf(p, f, 2.4022650696e-1f);
    p = fmaf(p, f, 6.9314718056e-1f);
    p = fmaf(p, f, 1.0f);
    return p * __int_as_float((n + 127) << 23);
}

// ---------------------------------------------------------------------------
__global__ __launch_bounds__(256) void split_f32(
    const float* __restrict__ in, __nv_bfloat16* __restrict__ hi,
    __nv_bfloat16* __restrict__ lo, int n4)
{
    const int i = blockIdx.x * blockDim.x + threadIdx.x;
    if (i >= n4) return;
    float4 x = ((const float4*)in)[i];
    __nv_bfloat162 h0 = __floats2bfloat162_rn(x.x, x.y);
    __nv_bfloat162 h1 = __floats2bfloat162_rn(x.z, x.w);
    float2 f0 = __bfloat1622float2(h0);
    float2 f1 = __bfloat1622float2(h1);
    ((__nv_bfloat162*)hi)[2*i]     = h0;
    ((__nv_bfloat162*)hi)[2*i + 1] = h1;
    ((__nv_bfloat162*)lo)[2*i]     = __floats2bfloat162_rn(x.x - f0.x, x.y - f0.y);
    ((__nv_bfloat162*)lo)[2*i + 1] = __floats2bfloat162_rn(x.z - f1.x, x.w - f1.y);
}

// ===========================================================================
// Split-bf16 HMMA GEMM (3-term compute), cp.async double-buffered.
// MODE 0: fp32 out + bias.
// MODE 1: fp16 head layout [bh][t][hd]      (Q and K)
// MODE 2: fp16 transposed head [bh][hd][t]  (V)
// ===========================================================================
#define GBUF (384 * KSTR)
#define GEMM_SMEM (2 * GBUF * 2)       // 110592 bytes

template <int MODE>
__global__ __launch_bounds__(256, 2) void gemm_hmma(
    const __nv_bfloat16* __restrict__ Ah, const __nv_bfloat16* __restrict__ Al,
    const __nv_bfloat16* __restrict__ Wh, const __nv_bfloat16* __restrict__ Wl,
    const float* __restrict__ bias, float* __restrict__ Cf,
    __half* __restrict__ Cx)
{
    extern __shared__ __nv_bfloat16 sm[];
    const uint32_t sbase = (uint32_t)__cvta_generic_to_shared(sm);

    const int tid = threadIdx.x, wid = tid >> 5, lane = tid & 31;
    const int g = lane >> 2, tig = lane & 3;
    const int m0 = blockIdx.y * 128, n0 = blockIdx.x * 64;

    const int ar = tid >> 1, ad0 = (tid & 1) * 32;
    const int wr = tid >> 2, wd0 = (tid & 3) * 16;

    const __nv_bfloat16* pa_src = Ah + (size_t)(m0 + ar) * D_ + ad0;
    const __nv_bfloat16* pl_src = Al + (size_t)(m0 + ar) * D_ + ad0;
    const __nv_bfloat16* pw_src = Wh + (size_t)(n0 + wr) * D_ + wd0;
    const __nv_bfloat16* pq_src = Wl + (size_t)(n0 + wr) * D_ + wd0;
    const uint32_t da = sbase + (uint32_t)(ar * KSTR + ad0) * 2;
    const uint32_t dw = sbase + (uint32_t)(256 * KSTR + wr * KSTR + wd0) * 2;

    auto prefetch = [&](int k0, int b) {
        const uint32_t off = (uint32_t)b * (GBUF * 2);
        const __nv_bfloat16* s;
        s = pa_src + k0;
#pragma unroll
        for (int u = 0; u < 4; u++) cpa16(da + off + u * 16, s + u * 8);
        s = pl_src + k0;
#pragma unroll
        for (int u = 0; u < 4; u++) cpa16(da + off + 128 * KSTR * 2 + u * 16, s + u * 8);
        s = pw_src + k0;
#pragma unroll
        for (int u = 0; u < 2; u++) cpa16(dw + off + u * 16, s + u * 8);
        s = pq_src + k0;
#pragma unroll
        for (int u = 0; u < 2; u++) cpa16(dw + off + 64 * KSTR * 2 + u * 16, s + u * 8);
    };

    float acc[8][4];
#pragma unroll
    for (int i = 0; i < 8; i++)
#pragma unroll
        for (int j = 0; j < 4; j++) acc[i][j] = 0.f;

    prefetch(0, 0);
    CP_COMMIT();

    for (int it = 0; it < 8; it++) {
        CP_WAIT0();
        __syncthreads();
        if (it + 1 < 8) { prefetch((it + 1) * 64, (it + 1) & 1); CP_COMMIT(); }

        const __nv_bfloat16* buf = sm + (it & 1) * GBUF;
        __nv_bfloat16 (*sAh)[KSTR] = (__nv_bfloat16(*)[KSTR])(buf);
        __nv_bfloat16 (*sAl)[KSTR] = (__nv_bfloat16(*)[KSTR])(buf + 128 * KSTR);
        __nv_bfloat16 (*sWh)[KSTR] = (__nv_bfloat16(*)[KSTR])(buf + 256 * KSTR);
        __nv_bfloat16 (*sWl)[KSTR] = (__nv_bfloat16(*)[KSTR])(buf + 320 * KSTR);

        uint32_t ah[4][4], al[4][4];
        const int r0 = wid * 16 + g;
#pragma unroll
        for (int kt = 0; kt < 4; kt++) {
            const int c0 = kt * 16 + tig * 2;
            ah[kt][0] = *(uint32_t*)&sAh[r0    ][c0    ];
            ah[kt][1] = *(uint32_t*)&sAh[r0 + 8][c0    ];
            ah[kt][2] = *(uint32_t*)&sAh[r0    ][c0 + 8];
            ah[kt][3] = *(uint32_t*)&sAh[r0 + 8][c0 + 8];
            al[kt][0] = *(uint32_t*)&sAl[r0    ][c0    ];
            al[kt][1] = *(uint32_t*)&sAl[r0 + 8][c0    ];
            al[kt][2] = *(uint32_t*)&sAl[r0    ][c0 + 8];
            al[kt][3] = *(uint32_t*)&sAl[r0 + 8][c0 + 8];
        }
#pragma unroll
        for (int nt = 0; nt < 8; nt++) {
            const int row = nt * 8 + g;
            uint32_t bh[4][2], bl[4][2];
#pragma unroll
            for (int kk = 0; kk < 4; kk++) {
                const int c = kk * 16 + tig * 2;
                bh[kk][0] = *(uint32_t*)&sWh[row][c];
                bh[kk][1] = *(uint32_t*)&sWh[row][c + 8];
                bl[kk][0] = *(uint32_t*)&sWl[row][c];
                bl[kk][1] = *(uint32_t*)&sWl[row][c + 8];
            }
#pragma unroll
            for (int kk = 0; kk < 4; kk++) mma16816(acc[nt], ah[kk], bh[kk]);
#pragma unroll
            for (int kk = 0; kk < 4; kk++) mma16816(acc[nt], al[kk], bh[kk]);
#pragma unroll
            for (int kk = 0; kk < 4; kk++) mma16816(acc[nt], ah[kk], bl[kk]);
        }
        __syncthreads();
    }

    const int gm = m0 + wid * 16 + g;
#pragma unroll
    for (int nt = 0; nt < 8; nt++) {
        const int n = n0 + nt * 8 + tig * 2;
        if (MODE == 0) {
            const float bx = bias[n], by = bias[n + 1];
            *(float2*)(Cf + (size_t)gm * D_ + n) =
                make_float2(acc[nt][0] + bx, acc[nt][1] + by);
            *(float2*)(Cf + (size_t)(gm + 8) * D_ + n) =
                make_float2(acc[nt][2] + bx, acc[nt][3] + by);
        } else if (MODE == 1) {      // fp16 head layout
            const int b = gm >> 12, t = gm & (T_ - 1);
            const int h = n >> 6, hd = n & 63;
            const size_t i0 = (((size_t)(b * H_ + h)) * T_ + t) * HD_ + hd;
            const size_t i1 = i0 + 8 * HD_;
            *(__half2*)(Cx + i0) = __floats2half2_rn(acc[nt][0], acc[nt][1]);
            *(__half2*)(Cx + i1) = __floats2half2_rn(acc[nt][2], acc[nt][3]);
        } else {                     // MODE 2: fp16 transposed V [bh][hd][t]
            const int b = gm >> 12, t = gm & (T_ - 1);
            const int h = n >> 6, hd = n & 63;
            const size_t r0i = (((size_t)(b * H_ + h)) * HD_ + hd) * T_;
#pragma unroll
            for (int e = 0; e < 2; e++) {
                const size_t ix = r0i + (size_t)e * T_ + t;
                Cx[ix]     = __float2half_rn(acc[nt][e]);
                Cx[ix + 8] = __float2half_rn(acc[nt][2 + e]);
            }
        }
    }
}

// ===========================================================================
// Causal flash attention, single-term fp16 HMMA:
//   S = qf . kf       (fp16, err ~5e-5 via softmax suppression)
//   O = pf . vf       (fp16, err ~3.9e-4)
// 16 MMAs per kt (was 40). cp.async double-buffered Kf/Vf tiles.
// ===========================================================================
#define BQ 128
#define BK 64
#define SBUF (2 * BK * KSTR)           // Kf + Vf per stage (half elems)
#define FLASH_SMEM (2 * SBUF * 2)      // 36864 bytes

__global__ __launch_bounds__(256, 3) void flash_mma(
    const __half* __restrict__ Qf, const __half* __restrict__ Kf,
    const __half* __restrict__ Vtf,
    __nv_bfloat16* __restrict__ Ch, __nv_bfloat16* __restrict__ Cl)
{
    extern __shared__ __half smh[];
    const uint32_t sbase = (uint32_t)__cvta_generic_to_shared(smh);

    const int tid  = threadIdx.x;
    const int wid  = tid >> 5, lane = tid & 31;
    const int g    = lane >> 2, tig = lane & 3;
    const int bh   = blockIdx.y;
    const int q0   = (gridDim.x - 1 - blockIdx.x) * BQ;

    const size_t base = (size_t)bh * T_ * HD_;
    const __half* Qg = Qf + base;
    const __half* Kg = Kf + base;
    const __half* Vg = Vtf + base;

    // ---- Stage Q through buffer-0, extract A frags (single fp16 set) ----
    __half (*qs)[KSTR] = (__half(*)[KSTR])(smh);
    uint32_t qf[4][4];
    const int cprow = tid >> 2;
    const int cpd0  = (tid & 3) * 16;
#pragma unroll
    for (int pb = 0; pb < 2; pb++) {
        if (pb) __syncthreads();
        {
            const __half* s0 = Qg + (size_t)(q0 + pb * 64 + cprow) * HD_ + cpd0;
            *(uint4*)&qs[cprow][cpd0]     = *(const uint4*)(s0);
            *(uint4*)&qs[cprow][cpd0 + 8] = *(const uint4*)(s0 + 8);
        }
        __syncthreads();
        if ((wid >> 2) == pb) {
            const int r0 = (wid & 3) * 16 + g;
#pragma unroll
            for (int kt = 0; kt < 4; kt++) {
                const int c0 = kt * 16 + tig * 2;
                qf[kt][0] = *(uint32_t*)&qs[r0    ][c0    ];
                qf[kt][1] = *(uint32_t*)&qs[r0 + 8][c0    ];
                qf[kt][2] = *(uint32_t*)&qs[r0    ][c0 + 8];
                qf[kt][3] = *(uint32_t*)&qs[r0 + 8][c0 + 8];
            }
        }
    }
    __syncthreads();

    const int pr = tid >> 2;            // 0..63
    const int pe = (tid & 3) * 16;      // half-elem offset: 0,16,32,48
    const __half* k_src = Kg + (size_t)pr * HD_ + pe;
    const __half* v_src = Vg + (size_t)pr * T_ + pe;
    const uint32_t drow = sbase + (uint32_t)(pr * KSTR + pe) * 2;

    auto prefetch = [&](int jt, int b) {
        const int k0 = jt * BK;
        const uint32_t d0 = drow + (uint32_t)b * (SBUF * 2);
        const __half* s;
        s = k_src + (size_t)k0 * HD_;
        cpa16(d0, s); cpa16(d0 + 16, s + 8);
        s = v_src + k0;
        cpa16(d0 + BK * KSTR * 2, s); cpa16(d0 + BK * KSTR * 2 + 16, s + 8);
    };

    float O[8][4];
#pragma unroll
    for (int i = 0; i < 8; i++)
#pragma unroll
        for (int j = 0; j < 4; j++) O[i][j] = 0.f;
    float l0 = 0.f, l1 = 0.f;

    const float SC = 0.18033688011112042f;   // log2(e)/sqrt(64)
    const int r0g = q0 + wid * 16 + g;
    const int r1g = r0g + 8;
    const int ntiles = (q0 >> 6) + 2;

    prefetch(0, 0);
    CP_COMMIT();

    for (int jt = 0; jt < ntiles; jt++) {
        const int k0 = jt * BK;
        CP_WAIT0();
        __syncthreads();
        if (jt + 1 < ntiles) { prefetch(jt + 1, (jt + 1) & 1); CP_COMMIT(); }

        __half (*cK)[KSTR] = (__half(*)[KSTR])(smh + (jt & 1) * SBUF);
        __half (*cV)[KSTR] = (__half(*)[KSTR])(smh + (jt & 1) * SBUF + BK * KSTR);

        if (jt == ntiles - 1 && wid < 4) continue;
        const bool needmask = (jt >= ntiles - 2);

#pragma unroll
        for (int kt = 0; kt < 4; kt++) {
            // ---- S both halves: 2 independent 4-chains ----
            float ca[2][4];
#pragma unroll
            for (int hf = 0; hf < 2; hf++)
#pragma unroll
                for (int r = 0; r < 4; r++) ca[hf][r] = 0.f;

            uint32_t bf[2][4][2];
            const int row0 = (2 * kt) * 8 + g, row1 = (2 * kt + 1) * 8 + g;
#pragma unroll
            for (int kk = 0; kk < 4; kk++) {
                const int col = kk * 16 + tig * 2;
                bf[0][kk][0] = *(uint32_t*)&cK[row0][col];
                bf[0][kk][1] = *(uint32_t*)&cK[row0][col + 8];
                bf[1][kk][0] = *(uint32_t*)&cK[row1][col];
                bf[1][kk][1] = *(uint32_t*)&cK[row1][col + 8];
            }
#pragma unroll
            for (int kk = 0; kk < 4; kk++) {
                mma16816h(ca[0], qf[kk], bf[0][kk]);
                mma16816h(ca[1], qf[kk], bf[1][kk]);
            }

            // ---- Softmax both halves, pack P fp16 ----
            uint32_t pa[4];
#pragma unroll
            for (int hf = 0; hf < 2; hf++) {
                const int kp = k0 + (2 * kt + hf) * 8 + tig * 2;
                float p00 = fexp2(ca[hf][0] * SC), p01 = fexp2(ca[hf][1] * SC);
                float p10 = fexp2(ca[hf][2] * SC), p11 = fexp2(ca[hf][3] * SC);
                if (needmask) {
                    if (kp     > r0g) p00 = 0.f;
                    if (kp + 1 > r0g) p01 = 0.f;
                    if (kp     > r1g) p10 = 0.f;
                    if (kp + 1 > r1g) p11 = 0.f;
                }
                l0 += p00 + p01;
                l1 += p10 + p11;
                __half2 h0 = __floats2half2_rn(p00, p01);
                __half2 h1 = __floats2half2_rn(p10, p11);
                pa[hf * 2 + 0] = *(uint32_t*)&h0;
                pa[hf * 2 + 1] = *(uint32_t*)&h1;
            }

            // ---- PV: 1 MMA per dn ----
#pragma unroll
            for (int dn = 0; dn < 8; dn++) {
                const int d = dn * 8 + g;
                const int c0 = kt * 16 + tig * 2;
                uint32_t bv[2];
                bv[0] = *(uint32_t*)&cV[d][c0];
                bv[1] = *(uint32_t*)&cV[d][c0 + 8];
                mma16816h(O[dn], pa, bv);
            }
        }
    }

    l0 += __shfl_xor_sync(0xffffffffu, l0, 1);
    l0 += __shfl_xor_sync(0xffffffffu, l0, 2);
    l1 += __shfl_xor_sync(0xffffffffu, l1, 1);
    l1 += __shfl_xor_sync(0xffffffffu, l1, 2);
    const float i0 = 1.0f / l0, i1 = 1.0f / l1;

    const int b = bh >> 3, h = bh & 7;
    const size_t o0 = ((size_t)(b * T_ + r0g)) * D_ + h * HD_;
    const size_t o1 = ((size_t)(b * T_ + r1g)) * D_ + h * HD_;
#pragma unroll
    for (int dn = 0; dn < 8; dn++) {
        const int d = dn * 8 + tig * 2;
        float a0 = O[dn][0] * i0, a1 = O[dn][1] * i0;
        float b0 = O[dn][2] * i1, b1 = O[dn][3] * i1;
        __nv_bfloat162 h0 = __floats2bfloat162_rn(a0, a1);
        __nv_bfloat162 h1 = __floats2bfloat162_rn(b0, b1);
        float2 f0 = __bfloat1622float2(h0);
        float2 f1 = __bfloat1622float2(h1);
        *(__nv_bfloat162*)(Ch + o0 + d) = h0;
        *(__nv_bfloat162*)(Ch + o1 + d) = h1;
        *(__nv_bfloat162*)(Cl + o0 + d) = __floats2bfloat162_rn(a0 - f0.x, a1 - f0.y);
        *(__nv_bfloat162*)(Cl + o1 + d) = __floats2bfloat162_rn(b0 - f1.x, b1 - f1.y);
    }
}

// ===========================================================================
extern "C" void kernel_launch(void* const* d_in, const int* in_sizes, int n_in,
                              void* d_out, int out_size)
{
    const float* x  = (const float*)d_in[0];
    const float* Wq = (const float*)d_in[1];
    const float* Wk = (const float*)d_in[2];
    const float* Wv = (const float*)d_in[3];
    const float* Wo = (const float*)d_in[4];
    const float* bo = (const float*)d_in[5];
    float* out = (float*)d_out;

    __half *qf, *kf, *vtf;
    __nv_bfloat16 *ch, *cl, *xh, *xl, *wh, *wl;
    cudaGetSymbolAddress((void**)&qf, g_qf);
    cudaGetSymbolAddress((void**)&kf, g_kf);
    cudaGetSymbolAddress((void**)&vtf, g_vtf);
    cudaGetSymbolAddress((void**)&ch, g_ch); cudaGetSymbolAddress((void**)&cl, g_cl);
    cudaGetSymbolAddress((void**)&xh, g_xh); cudaGetSymbolAddress((void**)&xl, g_xl);
    cudaGetSymbolAddress((void**)&wh, g_wh); cudaGetSymbolAddress((void**)&wl, g_wl);

    static bool attr_done = false;
    if (!attr_done) {
        cudaFuncSetAttribute(gemm_hmma<0>, cudaFuncAttributeMaxDynamicSharedMemorySize, GEMM_SMEM);
        cudaFuncSetAttribute(gemm_hmma<1>, cudaFuncAttributeMaxDynamicSharedMemorySize, GEMM_SMEM);
        cudaFuncSetAttribute(gemm_hmma<2>, cudaFuncAttributeMaxDynamicSharedMemorySize, GEMM_SMEM);
        cudaFuncSetAttribute(flash_mma, cudaFuncAttributeMaxDynamicSharedMemorySize, FLASH_SMEM);
        attr_done = true;
    }

    split_f32<<<(M_ * D_ / 4 + 255) / 256, 256>>>(x,  xh, xl, M_ * D_ / 4);
    split_f32<<<(D_ * D_ / 4 + 255) / 256, 256>>>(Wq, wh + 0 * (size_t)D_ * D_, wl + 0 * (size_t)D_ * D_, D_ * D_ / 4);
    split_f32<<<(D_ * D_ / 4 + 255) / 256, 256>>>(Wk, wh + 1 * (size_t)D_ * D_, wl + 1 * (size_t)D_ * D_, D_ * D_ / 4);
    split_f32<<<(D_ * D_ / 4 + 255) / 256, 256>>>(Wv, wh + 2 * (size_t)D_ * D_, wl + 2 * (size_t)D_ * D_, D_ * D_ / 4);
    split_f32<<<(D_ * D_ / 4 + 255) / 256, 256>>>(Wo, wh + 3 * (size_t)D_ * D_, wl + 3 * (size_t)D_ * D_, D_ * D_ / 4);

    dim3 ggrid(D_ / 64, M_ / 128);   // (8, 64)

    gemm_hmma<1><<<ggrid, 256, GEMM_SMEM>>>(xh, xl, wh + 0 * (size_t)D_ * D_, wl + 0 * (size_t)D_ * D_,
                                            nullptr, nullptr, qf);
    gemm_hmma<1><<<ggrid, 256, GEMM_SMEM>>>(xh, xl, wh + 1 * (size_t)D_ * D_, wl + 1 * (size_t)D_ * D_,
                                            nullptr, nullptr, kf);
    gemm_hmma<2><<<ggrid, 256, GEMM_SMEM>>>(xh, xl, wh + 2 * (size_t)D_ * D_, wl + 2 * (size_t)D_ * D_,
                                            nullptr, nullptr, vtf);

    dim3 agrid(T_ / BQ, B_ * H_);    // (32, 16)
    flash_mma<<<agrid, 256, FLASH_SMEM>>>(qf, kf, vtf, ch, cl);

    gemm_hmma<0><<<ggrid, 256, GEMM_SMEM>>>(ch, cl, wh + 3 * (size_t)D_ * D_, wl + 3 * (size_t)D_ * D_,
                                            bo, out, nullptr);
}

// round 17
// speedup vs baseline: 1.8163x; 1.1219x over previous
#include <cuda_runtime.h>
#include <cuda_bf16.h>
#include <cuda_fp16.h>
#include <cstdint>

#define B_  2
#define T_  4096
#define D_  512
#define H_  8
#define HD_ 64
#define M_  (B_*T_)
#define KSTR 72   // smem row stride (elems): conflict-free frag loads

// Scratch (allocation-free), all fp16
__device__ __half g_qf[B_*T_*D_];                  // Q fp16, head layout [bh][t][hd]
__device__ __half g_kf[B_*T_*D_];                  // K fp16, head layout
__device__ __half g_vtf[B_*T_*D_];                 // V fp16, transposed [bh][hd][T]
__device__ __half g_ch[B_*T_*D_], g_cl[B_*T_*D_];  // ctx fp16 hi/lo planes
__device__ __half g_xh[M_*D_],    g_xl[M_*D_];     // token_embed fp16 hi/lo
__device__ __half g_wf[4][D_*D_];                  // Wq,Wk,Wv,Wo single fp16

// ---------------------------------------------------------------------------
__device__ __forceinline__ void mma16816h(float* c, const uint32_t* a, const uint32_t* b) {
    asm volatile(
        "mma.sync.aligned.m16n8k16.row.col.f32.f16.f16.f32 "
        "{%0,%1,%2,%3}, {%4,%5,%6,%7}, {%8,%9}, {%0,%1,%2,%3};"
        : "+f"(c[0]), "+f"(c[1]), "+f"(c[2]), "+f"(c[3])
        : "r"(a[0]), "r"(a[1]), "r"(a[2]), "r"(a[3]), "r"(b[0]), "r"(b[1]));
}

__device__ __forceinline__ void cpa16(uint32_t dst, const void* src) {
    asm volatile("cp.async.cg.shared.global [%0], [%1], 16;" :: "r"(dst), "l"(src));
}
#define CP_COMMIT() asm volatile("cp.async.commit_group;" ::: "memory")
#define CP_WAIT0()  asm volatile("cp.async.wait_group 0;" ::: "memory")

__device__ __forceinline__ float fexp2(float x) {
    float t = x + 12582912.0f;
    int   n = __float_as_int(t) - __float_as_int(12582912.0f);
    float f = x - (t - 12582912.0f);
    float p = 1.3333558146e-3f;
    p = fmaf(p, f, 9.6181291076e-3f);
    p = fmaf(p, f, 5.5504108664e-2f);
    p = fmaf(p, f, 2.4022650696e-1f);
    p = fmaf(p, f, 6.9314718056e-1f);
    p = fmaf(p, f, 1.0f);
    return p * __int_as_float((n + 127) << 23);
}

// ---------------------------------------------------------------------------
// fp32 -> fp16 hi/lo planes (22-bit combined)
__global__ __launch_bounds__(256) void split_f32h(
    const float* __restrict__ in, __half* __restrict__ hi,
    __half* __restrict__ lo, int n4)
{
    const int i = blockIdx.x * blockDim.x + threadIdx.x;
    if (i >= n4) return;
    float4 x = ((const float4*)in)[i];
    __half2 h0 = __floats2half2_rn(x.x, x.y);
    __half2 h1 = __floats2half2_rn(x.z, x.w);
    float2 f0 = __half22float2(h0);
    float2 f1 = __half22float2(h1);
    ((__half2*)hi)[2*i]     = h0;
    ((__half2*)hi)[2*i + 1] = h1;
    ((__half2*)lo)[2*i]     = __floats2half2_rn(x.x - f0.x, x.y - f0.y);
    ((__half2*)lo)[2*i + 1] = __floats2half2_rn(x.z - f1.x, x.w - f1.y);
}

// fp32 -> single fp16
__global__ __launch_bounds__(256) void cvt_f32h(
    const float* __restrict__ in, __half* __restrict__ out, int n4)
{
    const int i = blockIdx.x * blockDim.x + threadIdx.x;
    if (i >= n4) return;
    float4 x = ((const float4*)in)[i];
    ((__half2*)out)[2*i]     = __floats2half2_rn(x.x, x.y);
    ((__half2*)out)[2*i + 1] = __floats2half2_rn(x.z, x.w);
}

// ===========================================================================
// 2-term fp16 HMMA GEMM: C = (Ah + Al) @ Wf^T, cp.async double-buffered.
// MODE 0: fp32 out + bias.
// MODE 1: fp16 head layout [bh][t][hd]      (Q and K)
// MODE 2: fp16 transposed head [bh][hd][t]  (V)
// ===========================================================================
#define GBUF (320 * KSTR)              // half elems per buffer (Ah,Al:128 rows each; W:64)
#define GEMM_SMEM (2 * GBUF * 2)       // 92160 bytes

template <int MODE>
__global__ __launch_bounds__(256, 2) void gemm_hmma(
    const __half* __restrict__ Ah, const __half* __restrict__ Al,
    const __half* __restrict__ Wf,
    const float* __restrict__ bias, float* __restrict__ Cf,
    __half* __restrict__ Cx)
{
    extern __shared__ __half sm[];
    const uint32_t sbase = (uint32_t)__cvta_generic_to_shared(sm);

    const int tid = threadIdx.x, wid = tid >> 5, lane = tid & 31;
    const int g = lane >> 2, tig = lane & 3;
    const int m0 = blockIdx.y * 128, n0 = blockIdx.x * 64;

    const int ar = tid >> 1, ad0 = (tid & 1) * 32;
    const int wr = tid >> 2, wd0 = (tid & 3) * 16;

    const __half* pa_src = Ah + (size_t)(m0 + ar) * D_ + ad0;
    const __half* pl_src = Al + (size_t)(m0 + ar) * D_ + ad0;
    const __half* pw_src = Wf + (size_t)(n0 + wr) * D_ + wd0;
    const uint32_t da = sbase + (uint32_t)(ar * KSTR + ad0) * 2;
    const uint32_t dw = sbase + (uint32_t)(256 * KSTR + wr * KSTR + wd0) * 2;

    auto prefetch = [&](int k0, int b) {
        const uint32_t off = (uint32_t)b * (GBUF * 2);
        const __half* s;
        s = pa_src + k0;
#pragma unroll
        for (int u = 0; u < 4; u++) cpa16(da + off + u * 16, s + u * 8);
        s = pl_src + k0;
#pragma unroll
        for (int u = 0; u < 4; u++) cpa16(da + off + 128 * KSTR * 2 + u * 16, s + u * 8);
        s = pw_src + k0;
#pragma unroll
        for (int u = 0; u < 2; u++) cpa16(dw + off + u * 16, s + u * 8);
    };

    float acc[8][4];
#pragma unroll
    for (int i = 0; i < 8; i++)
#pragma unroll
        for (int j = 0; j < 4; j++) acc[i][j] = 0.f;

    prefetch(0, 0);
    CP_COMMIT();

    for (int it = 0; it < 8; it++) {
        CP_WAIT0();
        __syncthreads();
        if (it + 1 < 8) { prefetch((it + 1) * 64, (it + 1) & 1); CP_COMMIT(); }

        const __half* buf = sm + (it & 1) * GBUF;
        __half (*sAh)[KSTR] = (__half(*)[KSTR])(buf);
        __half (*sAl)[KSTR] = (__half(*)[KSTR])(buf + 128 * KSTR);
        __half (*sW)[KSTR]  = (__half(*)[KSTR])(buf + 256 * KSTR);

        uint32_t ah[4][4], al[4][4];
        const int r0 = wid * 16 + g;
#pragma unroll
        for (int kt = 0; kt < 4; kt++) {
            const int c0 = kt * 16 + tig * 2;
            ah[kt][0] = *(uint32_t*)&sAh[r0    ][c0    ];
            ah[kt][1] = *(uint32_t*)&sAh[r0 + 8][c0    ];
            ah[kt][2] = *(uint32_t*)&sAh[r0    ][c0 + 8];
            ah[kt][3] = *(uint32_t*)&sAh[r0 + 8][c0 + 8];
            al[kt][0] = *(uint32_t*)&sAl[r0    ][c0    ];
            al[kt][1] = *(uint32_t*)&sAl[r0 + 8][c0    ];
            al[kt][2] = *(uint32_t*)&sAl[r0    ][c0 + 8];
            al[kt][3] = *(uint32_t*)&sAl[r0 + 8][c0 + 8];
        }
#pragma unroll
        for (int nt = 0; nt < 8; nt++) {
            const int row = nt * 8 + g;
            uint32_t bw[4][2];
#pragma unroll
            for (int kk = 0; kk < 4; kk++) {
                const int c = kk * 16 + tig * 2;
                bw[kk][0] = *(uint32_t*)&sW[row][c];
                bw[kk][1] = *(uint32_t*)&sW[row][c + 8];
            }
#pragma unroll
            for (int kk = 0; kk < 4; kk++) mma16816h(acc[nt], ah[kk], bw[kk]);
#pragma unroll
            for (int kk = 0; kk < 4; kk++) mma16816h(acc[nt], al[kk], bw[kk]);
        }
        __syncthreads();
    }

    const int gm = m0 + wid * 16 + g;
#pragma unroll
    for (int nt = 0; nt < 8; nt++) {
        const int n = n0 + nt * 8 + tig * 2;
        if (MODE == 0) {
            const float bx = bias[n], by = bias[n + 1];
            *(float2*)(Cf + (size_t)gm * D_ + n) =
                make_float2(acc[nt][0] + bx, acc[nt][1] + by);
            *(float2*)(Cf + (size_t)(gm + 8) * D_ + n) =
                make_float2(acc[nt][2] + bx, acc[nt][3] + by);
        } else if (MODE == 1) {      // fp16 head layout
            const int b = gm >> 12, t = gm & (T_ - 1);
            const int h = n >> 6, hd = n & 63;
            const size_t i0 = (((size_t)(b * H_ + h)) * T_ + t) * HD_ + hd;
            const size_t i1 = i0 + 8 * HD_;
            *(__half2*)(Cx + i0) = __floats2half2_rn(acc[nt][0], acc[nt][1]);
            *(__half2*)(Cx + i1) = __floats2half2_rn(acc[nt][2], acc[nt][3]);
        } else {                     // MODE 2: fp16 transposed V [bh][hd][t]
            const int b = gm >> 12, t = gm & (T_ - 1);
            const int h = n >> 6, hd = n & 63;
            const size_t r0i = (((size_t)(b * H_ + h)) * HD_ + hd) * T_;
#pragma unroll
            for (int e = 0; e < 2; e++) {
                const size_t ix = r0i + (size_t)e * T_ + t;
                Cx[ix]     = __float2half_rn(acc[nt][e]);
                Cx[ix + 8] = __float2half_rn(acc[nt][2 + e]);
            }
        }
    }
}

// ===========================================================================
// Causal flash attention, single-term fp16 HMMA (unchanged core from R14);
// epilogue now writes fp16 hi/lo ctx planes.
// ===========================================================================
#define BQ 128
#define BK 64
#define SBUF (2 * BK * KSTR)
#define FLASH_SMEM (2 * SBUF * 2)      // 36864 bytes

__global__ __launch_bounds__(256, 3) void flash_mma(
    const __half* __restrict__ Qf, const __half* __restrict__ Kf,
    const __half* __restrict__ Vtf,
    __half* __restrict__ Ch, __half* __restrict__ Cl)
{
    extern __shared__ __half smh[];
    const uint32_t sbase = (uint32_t)__cvta_generic_to_shared(smh);

    const int tid  = threadIdx.x;
    const int wid  = tid >> 5, lane = tid & 31;
    const int g    = lane >> 2, tig = lane & 3;
    const int bh   = blockIdx.y;
    const int q0   = (gridDim.x - 1 - blockIdx.x) * BQ;

    const size_t base = (size_t)bh * T_ * HD_;
    const __half* Qg = Qf + base;
    const __half* Kg = Kf + base;
    const __half* Vg = Vtf + base;

    // ---- Stage Q through buffer-0, extract A frags ----
    __half (*qs)[KSTR] = (__half(*)[KSTR])(smh);
    uint32_t qf[4][4];
    const int cprow = tid >> 2;
    const int cpd0  = (tid & 3) * 16;
#pragma unroll
    for (int pb = 0; pb < 2; pb++) {
        if (pb) __syncthreads();
        {
            const __half* s0 = Qg + (size_t)(q0 + pb * 64 + cprow) * HD_ + cpd0;
            *(uint4*)&qs[cprow][cpd0]     = *(const uint4*)(s0);
            *(uint4*)&qs[cprow][cpd0 + 8] = *(const uint4*)(s0 + 8);
        }
        __syncthreads();
        if ((wid >> 2) == pb) {
            const int r0 = (wid & 3) * 16 + g;
#pragma unroll
            for (int kt = 0; kt < 4; kt++) {
                const int c0 = kt * 16 + tig * 2;
                qf[kt][0] = *(uint32_t*)&qs[r0    ][c0    ];
                qf[kt][1] = *(uint32_t*)&qs[r0 + 8][c0    ];
                qf[kt][2] = *(uint32_t*)&qs[r0    ][c0 + 8];
                qf[kt][3] = *(uint32_t*)&qs[r0 + 8][c0 + 8];
            }
        }
    }
    __syncthreads();

    const int pr = tid >> 2;
    const int pe = (tid & 3) * 16;
    const __half* k_src = Kg + (size_t)pr * HD_ + pe;
    const __half* v_src = Vg + (size_t)pr * T_ + pe;
    const uint32_t drow = sbase + (uint32_t)(pr * KSTR + pe) * 2;

    auto prefetch = [&](int jt, int b) {
        const int k0 = jt * BK;
        const uint32_t d0 = drow + (uint32_t)b * (SBUF * 2);
        const __half* s;
        s = k_src + (size_t)k0 * HD_;
        cpa16(d0, s); cpa16(d0 + 16, s + 8);
        s = v_src + k0;
        cpa16(d0 + BK * KSTR * 2, s); cpa16(d0 + BK * KSTR * 2 + 16, s + 8);
    };

    float O[8][4];
#pragma unroll
    for (int i = 0; i < 8; i++)
#pragma unroll
        for (int j = 0; j < 4; j++) O[i][j] = 0.f;
    float l0 = 0.f, l1 = 0.f;

    const float SC = 0.18033688011112042f;
    const int r0g = q0 + wid * 16 + g;
    const int r1g = r0g + 8;
    const int ntiles = (q0 >> 6) + 2;

    prefetch(0, 0);
    CP_COMMIT();

    for (int jt = 0; jt < ntiles; jt++) {
        const int k0 = jt * BK;
        CP_WAIT0();
        __syncthreads();
        if (jt + 1 < ntiles) { prefetch(jt + 1, (jt + 1) & 1); CP_COMMIT(); }

        __half (*cK)[KSTR] = (__half(*)[KSTR])(smh + (jt & 1) * SBUF);
        __half (*cV)[KSTR] = (__half(*)[KSTR])(smh + (jt & 1) * SBUF + BK * KSTR);

        if (jt == ntiles - 1 && wid < 4) continue;
        const bool needmask = (jt >= ntiles - 2);

#pragma unroll
        for (int kt = 0; kt < 4; kt++) {
            float ca[2][4];
#pragma unroll
            for (int hf = 0; hf < 2; hf++)
#pragma unroll
                for (int r = 0; r < 4; r++) ca[hf][r] = 0.f;

            uint32_t bf[2][4][2];
            const int row0 = (2 * kt) * 8 + g, row1 = (2 * kt + 1) * 8 + g;
#pragma unroll
            for (int kk = 0; kk < 4; kk++) {
                const int col = kk * 16 + tig * 2;
                bf[0][kk][0] = *(uint32_t*)&cK[row0][col];
                bf[0][kk][1] = *(uint32_t*)&cK[row0][col + 8];
                bf[1][kk][0] = *(uint32_t*)&cK[row1][col];
                bf[1][kk][1] = *(uint32_t*)&cK[row1][col + 8];
            }
#pragma unroll
            for (int kk = 0; kk < 4; kk++) {
                mma16816h(ca[0], qf[kk], bf[0][kk]);
                mma16816h(ca[1], qf[kk], bf[1][kk]);
            }

            uint32_t pa[4];
#pragma unroll
            for (int hf = 0; hf < 2; hf++) {
                const int kp = k0 + (2 * kt + hf) * 8 + tig * 2;
                float p00 = fexp2(ca[hf][0] * SC), p01 = fexp2(ca[hf][1] * SC);
                float p10 = fexp2(ca[hf][2] * SC), p11 = fexp2(ca[hf][3] * SC);
                if (needmask) {
                    if (kp     > r0g) p00 = 0.f;
                    if (kp + 1 > r0g) p01 = 0.f;
                    if (kp     > r1g) p10 = 0.f;
                    if (kp + 1 > r1g) p11 = 0.f;
                }
                l0 += p00 + p01;
                l1 += p10 + p11;
                __half2 h0 = __floats2half2_rn(p00, p01);
                __half2 h1 = __floats2half2_rn(p10, p11);
                pa[hf * 2 + 0] = *(uint32_t*)&h0;
                pa[hf * 2 + 1] = *(uint32_t*)&h1;
            }

#pragma unroll
            for (int dn = 0; dn < 8; dn++) {
                const int d = dn * 8 + g;
                const int c0 = kt * 16 + tig * 2;
                uint32_t bv[2];
                bv[0] = *(uint32_t*)&cV[d][c0];
                bv[1] = *(uint32_t*)&cV[d][c0 + 8];
                mma16816h(O[dn], pa, bv);
            }
        }
    }

    l0 += __shfl_xor_sync(0xffffffffu, l0, 1);
    l0 += __shfl_xor_sync(0xffffffffu, l0, 2);
    l1 += __shfl_xor_sync(0xffffffffu, l1, 1);
    l1 += __shfl_xor_sync(0xffffffffu, l1, 2);
    const float i0 = 1.0f / l0, i1 = 1.0f / l1;

    const int b = bh >> 3, h = bh & 7;
    const size_t o0 = ((size_t)(b * T_ + r0g)) * D_ + h * HD_;
    const size_t o1 = ((size_t)(b * T_ + r1g)) * D_ + h * HD_;
#pragma unroll
    for (int dn = 0; dn < 8; dn++) {
        const int d = dn * 8 + tig * 2;
        float a0 = O[dn][0] * i0, a1 = O[dn][1] * i0;
        float b0 = O[dn][2] * i1, b1 = O[dn][3] * i1;
        __half2 h0 = __floats2half2_rn(a0, a1);
        __half2 h1 = __floats2half2_rn(b0, b1);
        float2 f0 = __half22float2(h0);
        float2 f1 = __half22float2(h1);
        *(__half2*)(Ch + o0 + d) = h0;
        *(__half2*)(Ch + o1 + d) = h1;
        *(__half2*)(Cl + o0 + d) = __floats2half2_rn(a0 - f0.x, a1 - f0.y);
        *(__half2*)(Cl + o1 + d) = __floats2half2_rn(b0 - f1.x, b1 - f1.y);
    }
}

// ===========================================================================
extern "C" void kernel_launch(void* const* d_in, const int* in_sizes, int n_in,
                              void* d_out, int out_size)
{
    const float* x  = (const float*)d_in[0];
    const float* Wq = (const float*)d_in[1];
    const float* Wk = (const float*)d_in[2];
    const float* Wv = (const float*)d_in[3];
    const float* Wo = (const float*)d_in[4];
    const float* bo = (const float*)d_in[5];
    float* out = (float*)d_out;

    __half *qf, *kf, *vtf, *ch, *cl, *xh, *xl, *wf;
    cudaGetSymbolAddress((void**)&qf, g_qf);
    cudaGetSymbolAddress((void**)&kf, g_kf);
    cudaGetSymbolAddress((void**)&vtf, g_vtf);
    cudaGetSymbolAddress((void**)&ch, g_ch); cudaGetSymbolAddress((void**)&cl, g_cl);
    cudaGetSymbolAddress((void**)&xh, g_xh); cudaGetSymbolAddress((void**)&xl, g_xl);
    cudaGetSymbolAddress((void**)&wf, g_wf);

    static bool attr_done = false;
    if (!attr_done) {
        cudaFuncSetAttribute(gemm_hmma<0>, cudaFuncAttributeMaxDynamicSharedMemorySize, GEMM_SMEM);
        cudaFuncSetAttribute(gemm_hmma<1>, cudaFuncAttributeMaxDynamicSharedMemorySize, GEMM_SMEM);
        cudaFuncSetAttribute(gemm_hmma<2>, cudaFuncAttributeMaxDynamicSharedMemorySize, GEMM_SMEM);
        cudaFuncSetAttribute(flash_mma, cudaFuncAttributeMaxDynamicSharedMemorySize, FLASH_SMEM);
        attr_done = true;
    }

    split_f32h<<<(M_ * D_ / 4 + 255) / 256, 256>>>(x, xh, xl, M_ * D_ / 4);
    cvt_f32h<<<(D_ * D_ / 4 + 255) / 256, 256>>>(Wq, wf + 0 * (size_t)D_ * D_, D_ * D_ / 4);
    cvt_f32h<<<(D_ * D_ / 4 + 255) / 256, 256>>>(Wk, wf + 1 * (size_t)D_ * D_, D_ * D_ / 4);
    cvt_f32h<<<(D_ * D_ / 4 + 255) / 256, 256>>>(Wv, wf + 2 * (size_t)D_ * D_, D_ * D_ / 4);
    cvt_f32h<<<(D_ * D_ / 4 + 255) / 256, 256>>>(Wo, wf + 3 * (size_t)D_ * D_, D_ * D_ / 4);

    dim3 ggrid(D_ / 64, M_ / 128);   // (8, 64)

    gemm_hmma<1><<<ggrid, 256, GEMM_SMEM>>>(xh, xl, wf + 0 * (size_t)D_ * D_, nullptr, nullptr, qf);
    gemm_hmma<1><<<ggrid, 256, GEMM_SMEM>>>(xh, xl, wf + 1 * (size_t)D_ * D_, nullptr, nullptr, kf);
    gemm_hmma<2><<<ggrid, 256, GEMM_SMEM>>>(xh, xl, wf + 2 * (size_t)D_ * D_, nullptr, nullptr, vtf);

    dim3 agrid(T_ / BQ, B_ * H_);    // (32, 16)
    flash_mma<<<agrid, 256, FLASH_SMEM>>>(qf, kf, vtf, ch, cl);

    gemm_hmma<0><<<ggrid, 256, GEMM_SMEM>>>(ch, cl, wf + 3 * (size_t)D_ * D_, bo, out, nullptr);
}